// round 15
// baseline (speedup 1.0000x reference)
#include <cuda_runtime.h>
#include <cuda_bf16.h>

#define Bc   2
#define Sc   2048
#define Dc   1024
#define Hc   16
#define DKc  64
#define Mc   (Bc * Sc)        // 4096
#define BHc  (Bc * Hc)        // 32

// exp(0.125*x) == 2^(x * 0.125*log2(e))
#define EXP_SCALE 0.18033688011112042f

// attn dynamic smem layout (bytes):
//   setup : qs   f32[128][68]                @0      (34816)
//   pass1 : kb0  bf16[128][72] @0, kb1 @18432        (36864)
//   pass2 : ks0  f32[128][68] @0, ks1 @34816         (69632)
//           vs[4] bf16[64][72] @69632 + i*9216       (36864)
#define ATTN_SMEM 106496

// ---------------------------------------------------------------------------
// Scratch (__device__ globals; no cudaMalloc allowed)
// ---------------------------------------------------------------------------
__device__ __align__(16) __nv_bfloat16 g_xb [(size_t)Mc * Dc];          // X bf16 (V path)
__device__ __align__(16) float         g_xtf[(size_t)Mc * Dc];          // X tf32-rounded (QK path)
__device__ __align__(16) __nv_bfloat16 g_wT [4][(size_t)Dc * Dc];       // bf16 W^T ([2],[3] used)
__device__ __align__(16) float         g_wTf[2][(size_t)Dc * Dc];       // tf32-rounded W^T (Wq,Wk)
__device__ __align__(16) float         g_qf [(size_t)BHc * Sc * DKc];   // q tf32-rounded [bh][s][dk]
__device__ __align__(16) float         g_kf [(size_t)BHc * Sc * DKc];   // k tf32-rounded [bh][s][dk]
__device__ __align__(16) __nv_bfloat16 g_kb [(size_t)BHc * Sc * DKc];   // k bf16 (pass-1 sums)
__device__ __align__(16) __nv_bfloat16 g_vT [(size_t)BHc * DKc * Sc];   // v bf16 [bh][dk][s]
__device__ __align__(16) __nv_bfloat16 g_ctxb[(size_t)Mc * Dc];         // ctx bf16
__device__ unsigned g_mask[(size_t)Bc * Sc * (Sc / 32)];                 // bit-packed mask
__device__ __align__(16) float g_y [(size_t)Mc * Dc];                    // pre-LN

// ---------------------------------------------------------------------------
// MMA + async-copy + ldmatrix helpers
// ---------------------------------------------------------------------------
__device__ __forceinline__ void mma_bf16(
    float& c0, float& c1, float& c2, float& c3,
    unsigned a0, unsigned a1, unsigned a2, unsigned a3,
    unsigned b0, unsigned b1)
{
    asm volatile(
        "mma.sync.aligned.m16n8k16.row.col.f32.bf16.bf16.f32 "
        "{%0,%1,%2,%3}, {%4,%5,%6,%7}, {%8,%9}, {%0,%1,%2,%3};\n"
        : "+f"(c0), "+f"(c1), "+f"(c2), "+f"(c3)
        : "r"(a0), "r"(a1), "r"(a2), "r"(a3), "r"(b0), "r"(b1));
}

__device__ __forceinline__ void mma_tf32(
    float& c0, float& c1, float& c2, float& c3,
    unsigned a0, unsigned a1, unsigned a2, unsigned a3,
    unsigned b0, unsigned b1)
{
    asm volatile(
        "mma.sync.aligned.m16n8k8.row.col.f32.tf32.tf32.f32 "
        "{%0,%1,%2,%3}, {%4,%5,%6,%7}, {%8,%9}, {%0,%1,%2,%3};\n"
        : "+f"(c0), "+f"(c1), "+f"(c2), "+f"(c3)
        : "r"(a0), "r"(a1), "r"(a2), "r"(a3), "r"(b0), "r"(b1));
}

__device__ __forceinline__ float f2tf_f(float x)
{
    unsigned r;
    asm("cvt.rna.tf32.f32 %0, %1;" : "=r"(r) : "f"(x));
    return __uint_as_float(r);
}

__device__ __forceinline__ unsigned pack_bf16x2(float a, float b)
{
    unsigned r;
    asm("cvt.rn.bf16x2.f32 %0, %1, %2;" : "=r"(r) : "f"(b), "f"(a));
    return r;
}

__device__ __forceinline__ float ex2(float x)
{
    float r;
    asm("ex2.approx.f32 %0, %1;" : "=f"(r) : "f"(x));
    return r;
}

__device__ __forceinline__ void cp16(void* smem, const void* gmem)
{
    unsigned sa = (unsigned)__cvta_generic_to_shared(smem);
    asm volatile("cp.async.cg.shared.global [%0], [%1], 16;\n"
                 :: "r"(sa), "l"(gmem));
}
__device__ __forceinline__ void cp_commit()
{
    asm volatile("cp.async.commit_group;\n");
}
template<int N> __device__ __forceinline__ void cp_wait()
{
    asm volatile("cp.async.wait_group %0;\n" :: "n"(N));
}

__device__ __forceinline__ void ldm_x4(unsigned& r0, unsigned& r1,
                                       unsigned& r2, unsigned& r3, const void* p)
{
    unsigned a = (unsigned)__cvta_generic_to_shared(p);
    asm volatile("ldmatrix.sync.aligned.m8n8.x4.shared.b16 {%0,%1,%2,%3}, [%4];\n"
                 : "=r"(r0), "=r"(r1), "=r"(r2), "=r"(r3) : "r"(a));
}

__device__ __forceinline__ void stcs2(float* p, float a, float b)
{
    asm volatile("st.global.cs.v2.f32 [%0], {%1, %2};\n"
                 :: "l"(p), "f"(a), "f"(b) : "memory");
}

// ---------------------------------------------------------------------------
// Kernel 0: merged pre-pass.
// ---------------------------------------------------------------------------
__global__ __launch_bounds__(256) void pre_kernel(
    const float* __restrict__ X, const unsigned* __restrict__ mask,
    const float* __restrict__ W0, const float* __restrict__ W1,
    const float* __restrict__ W2, const float* __restrict__ W3)
{
    __shared__ float tile[32][33];
    const int bid = blockIdx.x;
    const int tid = threadIdx.x;

    if (bid < 4096) {
        size_t i = ((size_t)bid * 256 + tid) * 4;
        float4 v = *(const float4*)(X + i);
        __nv_bfloat162* d = (__nv_bfloat162*)(g_xb + i);
        d[0] = __floats2bfloat162_rn(v.x, v.y);
        d[1] = __floats2bfloat162_rn(v.z, v.w);
        float4 tv = make_float4(f2tf_f(v.x), f2tf_f(v.y), f2tf_f(v.z), f2tf_f(v.w));
        *(float4*)(g_xtf + i) = tv;
    } else if (bid < 8192) {
        const int wb = bid - 4096;
        const int z  = wb >> 10;
        const int li = wb & 1023;
        const float* W = z == 0 ? W0 : z == 1 ? W1 : z == 2 ? W2 : W3;
        const int tx = tid & 31, ty = tid >> 5;
        const int k0 = (li & 31) * 32, n0 = (li >> 5) * 32;
        #pragma unroll
        for (int i = 0; i < 4; ++i)
            tile[ty + i * 8][tx] = W[(size_t)(k0 + ty + i * 8) * Dc + n0 + tx];
        __syncthreads();
        if (z < 2) {
            float* out = g_wTf[z];
            #pragma unroll
            for (int i = 0; i < 4; ++i)
                out[(size_t)(n0 + ty + i * 8) * Dc + k0 + tx] =
                    f2tf_f(tile[tx][ty + i * 8]);
        } else {
            __nv_bfloat16* out = g_wT[z];
            #pragma unroll
            for (int i = 0; i < 4; ++i)
                out[(size_t)(n0 + ty + i * 8) * Dc + k0 + tx] =
                    __float2bfloat16(tile[tx][ty + i * 8]);
        }
    } else {
        const int mb   = bid - 8192;           // 0..2047, 128 words each
        const int warp = tid >> 5, lane = tid & 31;
        const int wbase = mb * 128 + warp * 16;
        #pragma unroll
        for (int k = 0; k < 16; ++k) {
            const int w = wbase + k;
            unsigned v = mask[(size_t)w * 32 + lane];
            unsigned bits = __ballot_sync(0xffffffffu, v != 0);
            if (lane == 0) g_mask[w] = bits;
        }
    }
}

// ---------------------------------------------------------------------------
// Kernel 1: ALL projections in one launch.
//   z=0: q (tf32, BK=16), z=1: k (tf32, + bf16 copy), z=2: v (bf16, BK=32).
// ---------------------------------------------------------------------------
__global__ __launch_bounds__(256, 2) void proj_all_kernel(
    const float* __restrict__ bq, const float* __restrict__ bk,
    const float* __restrict__ bv)
{
    __shared__ __align__(16) unsigned char smA[20480];
    __shared__ __align__(16) unsigned char smB[20480];

    const int z    = blockIdx.z;
    const int tid  = threadIdx.x;
    const int warp = tid >> 5, lane = tid & 31;
    const int g = lane >> 2, t = lane & 3;
    const int wm = warp >> 1, wn = warp & 1;
    const int row0 = blockIdx.y * 128;
    const int col0 = blockIdx.x * 128;

    float c[2][8][4];
    #pragma unroll
    for (int mt = 0; mt < 2; ++mt)
        #pragma unroll
        for (int nt = 0; nt < 8; ++nt)
            #pragma unroll
            for (int q = 0; q < 4; ++q) c[mt][nt][q] = 0.f;

    if (z < 2) {
        const float* Wt   = g_wTf[z];
        const float* bias = z == 0 ? bq : bk;
        float* outp = z == 0 ? g_qf : g_kf;

        float (*as)[128][20] = (float (*)[128][20])smA;
        float (*bs)[128][20] = (float (*)[128][20])smB;

        auto load_stage = [&](int kk, int st) {
            #pragma unroll
            for (int it = 0; it < 2; ++it) {
                int f = tid + it * 256;
                int r = f >> 2, c4 = (f & 3) * 4;
                cp16(&as[st][r][c4], g_xtf + (size_t)(row0 + r) * Dc + kk + c4);
                cp16(&bs[st][r][c4], Wt    + (size_t)(col0 + r) * Dc + kk + c4);
            }
            cp_commit();
        };

        load_stage(0, 0);
        const int nT = Dc / 16;
        for (int tt = 0; tt < nT; ++tt) {
            const int cur = tt & 1;
            if (tt + 1 < nT) { load_stage((tt + 1) * 16, cur ^ 1); cp_wait<1>(); }
            else             { cp_wait<0>(); }
            __syncthreads();

            #pragma unroll
            for (int kf = 0; kf < 2; ++kf) {
                const int k0 = kf * 8;
                unsigned A[2][4];
                #pragma unroll
                for (int mt = 0; mt < 2; ++mt) {
                    int r = wm * 32 + mt * 16 + g;
                    A[mt][0] = __float_as_uint(as[cur][r    ][k0 + t]);
                    A[mt][1] = __float_as_uint(as[cur][r + 8][k0 + t]);
                    A[mt][2] = __float_as_uint(as[cur][r    ][k0 + t + 4]);
                    A[mt][3] = __float_as_uint(as[cur][r + 8][k0 + t + 4]);
                }
                #pragma unroll
                for (int nt = 0; nt < 8; ++nt) {
                    int n = wn * 64 + nt * 8 + g;
                    unsigned b0 = __float_as_uint(bs[cur][n][k0 + t]);
                    unsigned b1 = __float_as_uint(bs[cur][n][k0 + t + 4]);
                    mma_tf32(c[0][nt][0], c[0][nt][1], c[0][nt][2], c[0][nt][3],
                             A[0][0], A[0][1], A[0][2], A[0][3], b0, b1);
                    mma_tf32(c[1][nt][0], c[1][nt][1], c[1][nt][2], c[1][nt][3],
                             A[1][0], A[1][1], A[1][2], A[1][3], b0, b1);
                }
            }
            __syncthreads();
        }

        #pragma unroll
        for (int mt = 0; mt < 2; ++mt) {
            #pragma unroll
            for (int nt = 0; nt < 8; ++nt) {
                const int col = col0 + wn * 64 + nt * 8 + t * 2;
                const int h = col >> 6, dk = col & 63;
                const float bi0 = bias[col], bi1 = bias[col + 1];
                const int r0 = row0 + wm * 32 + mt * 16 + g;
                #pragma unroll
                for (int rr = 0; rr < 2; ++rr) {
                    const int rowg = r0 + rr * 8;
                    const int b = rowg >> 11, s = rowg & 2047;
                    const float v0 = c[mt][nt][rr * 2 + 0] + bi0;
                    const float v1 = c[mt][nt][rr * 2 + 1] + bi1;
                    const size_t off = ((size_t)(b * Hc + h) * Sc + s) * DKc + dk;
                    *(float2*)(outp + off) = make_float2(f2tf_f(v0), f2tf_f(v1));
                    if (z == 1)
                        *(__nv_bfloat162*)(g_kb + off) = __floats2bfloat162_rn(v0, v1);
                }
            }
        }
    } else {
        const __nv_bfloat16* Wt = g_wT[2];

        __nv_bfloat16 (*as)[128][40] = (__nv_bfloat16 (*)[128][40])smA;
        __nv_bfloat16 (*bs)[128][40] = (__nv_bfloat16 (*)[128][40])smB;

        auto load_stage = [&](int kk, int st) {
            #pragma unroll
            for (int it = 0; it < 2; ++it) {
                int f = tid + it * 256;
                int r = f >> 2, c8 = (f & 3) * 8;
                cp16(&as[st][r][c8], g_xb + (size_t)(row0 + r) * Dc + kk + c8);
                cp16(&bs[st][r][c8], Wt   + (size_t)(col0 + r) * Dc + kk + c8);
            }
            cp_commit();
        };

        load_stage(0, 0);
        const int nT = Dc / 32;
        for (int tt = 0; tt < nT; ++tt) {
            const int cur = tt & 1;
            if (tt + 1 < nT) { load_stage((tt + 1) * 32, cur ^ 1); cp_wait<1>(); }
            else             { cp_wait<0>(); }
            __syncthreads();

            #pragma unroll
            for (int kf = 0; kf < 2; ++kf) {
                const int k0 = kf * 16;
                unsigned A[2][4];
                #pragma unroll
                for (int mt = 0; mt < 2; ++mt) {
                    int r = wm * 32 + mt * 16 + g;
                    A[mt][0] = *(const unsigned*)&as[cur][r    ][k0     + t * 2];
                    A[mt][1] = *(const unsigned*)&as[cur][r + 8][k0     + t * 2];
                    A[mt][2] = *(const unsigned*)&as[cur][r    ][k0 + 8 + t * 2];
                    A[mt][3] = *(const unsigned*)&as[cur][r + 8][k0 + 8 + t * 2];
                }
                #pragma unroll
                for (int nt = 0; nt < 8; ++nt) {
                    int n = wn * 64 + nt * 8 + g;
                    unsigned b0 = *(const unsigned*)&bs[cur][n][k0     + t * 2];
                    unsigned b1 = *(const unsigned*)&bs[cur][n][k0 + 8 + t * 2];
                    mma_bf16(c[0][nt][0], c[0][nt][1], c[0][nt][2], c[0][nt][3],
                             A[0][0], A[0][1], A[0][2], A[0][3], b0, b1);
                    mma_bf16(c[1][nt][0], c[1][nt][1], c[1][nt][2], c[1][nt][3],
                             A[1][0], A[1][1], A[1][2], A[1][3], b0, b1);
                }
            }
            __syncthreads();
        }

        #pragma unroll
        for (int mt = 0; mt < 2; ++mt) {
            #pragma unroll
            for (int nt = 0; nt < 8; ++nt) {
                const int col = col0 + wn * 64 + nt * 8 + t * 2;
                const int h = col >> 6, dk = col & 63;
                const float bi0 = bv[col], bi1 = bv[col + 1];
                const int r0 = row0 + wm * 32 + mt * 16 + g;
                #pragma unroll
                for (int rr = 0; rr < 2; ++rr) {
                    const int rowg = r0 + rr * 8;
                    const int b = rowg >> 11, s = rowg & 2047;
                    g_vT[((size_t)(b * Hc + h) * DKc + dk    ) * Sc + s] =
                        __float2bfloat16(c[mt][nt][rr * 2 + 0] + bi0);
                    g_vT[((size_t)(b * Hc + h) * DKc + dk + 1) * Sc + s] =
                        __float2bfloat16(c[mt][nt][rr * 2 + 1] + bi1);
                }
            }
        }
    }
}

// ---------------------------------------------------------------------------
// Kernel 2: FUSED attention, dynamic smem (106 KB), 2 blocks/SM.
//   pass 1: bf16 q.k^T on 128-row K tiles (ldmatrix B) -> masked-exp row sums.
//   pass 2: tf32 q.k^T on 128-row K tiles with double-buffered {K,V} groups
//           (V latency hidden) -> p = e/l, streaming-store p, p @ V.
// ---------------------------------------------------------------------------
__global__ __launch_bounds__(256, 2) void attn_fused_kernel(float* __restrict__ attn)
{
    extern __shared__ __align__(16) unsigned char sbuf[];
    float (*qs)[68] = (float (*)[68])sbuf;
    __nv_bfloat16 (*kb0)[72] = (__nv_bfloat16 (*)[72])sbuf;
    __nv_bfloat16 (*kb1)[72] = (__nv_bfloat16 (*)[72])(sbuf + 18432);
    float (*ks0)[68] = (float (*)[68])sbuf;
    float (*ks1)[68] = (float (*)[68])(sbuf + 34816);

    const int bh = blockIdx.y;
    const int i0 = blockIdx.x * 128;
    const int b  = bh >> 4, h = bh & 15;

    const int tid = threadIdx.x, warp = tid >> 5, lane = tid & 31;
    const int g = lane >> 2, t = lane & 3;
    const int lm = lane >> 3, lr = lane & 7;

    const float* qbase = g_qf + ((size_t)bh * Sc + i0) * DKc;
    const float* kbase = g_kf + (size_t)bh * Sc * DKc;
    const __nv_bfloat16* kbbase = g_kb + (size_t)bh * Sc * DKc;
    const __nv_bfloat16* vbase  = g_vT + (size_t)bh * DKc * Sc;

    #pragma unroll
    for (int it = 0; it < 8; ++it) {
        int f = tid + it * 256;
        int r = f >> 4, c4 = (f & 15) * 4;
        *(float4*)&qs[r][c4] = *(const float4*)(qbase + (size_t)r * DKc + c4);
    }
    __syncthreads();

    unsigned A[8][4];    // tf32 fragments (pass 2)
    unsigned Ab[4][4];   // bf16 fragments (pass 1)
    {
        const int r = warp * 16 + g;
        #pragma unroll
        for (int kf = 0; kf < 8; ++kf) {
            const int k0 = kf * 8;
            A[kf][0] = __float_as_uint(qs[r    ][k0 + t]);
            A[kf][1] = __float_as_uint(qs[r + 8][k0 + t]);
            A[kf][2] = __float_as_uint(qs[r    ][k0 + t + 4]);
            A[kf][3] = __float_as_uint(qs[r + 8][k0 + t + 4]);
        }
        #pragma unroll
        for (int kf = 0; kf < 4; ++kf) {
            const int k0 = kf * 16;
            Ab[kf][0] = pack_bf16x2(qs[r    ][k0     + t * 2], qs[r    ][k0     + t * 2 + 1]);
            Ab[kf][1] = pack_bf16x2(qs[r + 8][k0     + t * 2], qs[r + 8][k0     + t * 2 + 1]);
            Ab[kf][2] = pack_bf16x2(qs[r    ][k0 + 8 + t * 2], qs[r    ][k0 + 8 + t * 2 + 1]);
            Ab[kf][3] = pack_bf16x2(qs[r + 8][k0 + 8 + t * 2], qs[r + 8][k0 + 8 + t * 2 + 1]);
        }
    }
    __syncthreads();

    const int ig0 = i0 + warp * 16 + g;
    const int ig1 = ig0 + 8;
    const unsigned* mp0 = g_mask + ((size_t)b * Sc + ig0) * (Sc / 32);
    const unsigned* mp1 = g_mask + ((size_t)b * Sc + ig1) * (Sc / 32);
    float* arow0 = attn + ((size_t)bh * Sc + ig0) * Sc;
    float* arow1 = attn + ((size_t)bh * Sc + ig1) * Sc;

    auto load_kb128 = [&](int jj, int st) {   // 128 rows of bf16 K (pass 1)
        __nv_bfloat16 (*dst)[72] = st ? kb1 : kb0;
        #pragma unroll
        for (int it = 0; it < 4; ++it) {
            int f = tid + it * 256;
            int r = f >> 3, c8 = (f & 7) * 8;
            cp16(&dst[r][c8], kbbase + (size_t)(jj + r) * DKc + c8);
        }
        cp_commit();
    };
    // pass 2: one group = 128-row fp32 K tile + both 64-row V subtiles
    auto load_kv = [&](int jj, int st) {
        float (*kdst)[68] = st ? ks1 : ks0;
        #pragma unroll
        for (int it = 0; it < 8; ++it) {
            int f = tid + it * 256;
            int r = f >> 4, c4 = (f & 15) * 4;
            cp16(&kdst[r][c4], kbase + (size_t)(jj + r) * DKc + c4);
        }
        #pragma unroll
        for (int sub = 0; sub < 2; ++sub) {
            __nv_bfloat16 (*vdst)[72] =
                (__nv_bfloat16 (*)[72])(sbuf + 69632 + (st * 2 + sub) * 9216);
            #pragma unroll
            for (int it = 0; it < 2; ++it) {
                int f = tid + it * 256;
                int dk = f >> 3, c8 = (f & 7) * 8;
                cp16(&vdst[dk][c8], vbase + (size_t)dk * Sc + jj + sub * 64 + c8);
            }
        }
        cp_commit();
    };

    // ---------------- pass 1: row sums (bf16 MMA, 128-row tiles) ------------
    float rsum0 = 0.f, rsum1 = 0.f;
    load_kb128(0, 0);
    for (int jj = 0; jj < Sc; jj += 128) {
        const int cur = (jj >> 7) & 1;
        if (jj + 128 < Sc) { load_kb128(jj + 128, cur ^ 1); cp_wait<1>(); }
        else               { cp_wait<0>(); }
        __syncthreads();
        __nv_bfloat16 (*kb)[72] = cur ? kb1 : kb0;

        #pragma unroll
        for (int sub = 0; sub < 2; ++sub) {
            const int jje = jj + sub * 64;
            __nv_bfloat16 (*kbs)[72] = (__nv_bfloat16 (*)[72])(kb + sub * 64);

            float c[8][4];
            #pragma unroll
            for (int nt = 0; nt < 8; ++nt)
                #pragma unroll
                for (int q = 0; q < 4; ++q) c[nt][q] = 0.f;
            #pragma unroll
            for (int kf = 0; kf < 4; ++kf) {
                const int k0 = kf * 16;
                #pragma unroll
                for (int q = 0; q < 4; ++q) {
                    const int nt0 = 2 * q;
                    unsigned r0, r1, r2, r3;
                    ldm_x4(r0, r1, r2, r3,
                           &kbs[(nt0 + (lm >> 1)) * 8 + lr][k0 + (lm & 1) * 8]);
                    mma_bf16(c[nt0][0], c[nt0][1], c[nt0][2], c[nt0][3],
                             Ab[kf][0], Ab[kf][1], Ab[kf][2], Ab[kf][3], r0, r1);
                    mma_bf16(c[nt0 + 1][0], c[nt0 + 1][1], c[nt0 + 1][2], c[nt0 + 1][3],
                             Ab[kf][0], Ab[kf][1], Ab[kf][2], Ab[kf][3], r2, r3);
                }
            }

            const unsigned m00 = mp0[jje >> 5], m01 = mp0[(jje >> 5) + 1];
            const unsigned m10 = mp1[jje >> 5], m11 = mp1[(jje >> 5) + 1];
            #pragma unroll
            for (int nt = 0; nt < 8; ++nt) {
                const int jl = nt * 8 + t * 2;
                const unsigned w0 = (jl & 32) ? m01 : m00;
                const unsigned w1 = (jl & 32) ? m11 : m10;
                const int sh = jl & 31;
                rsum0 += (((w0 >> sh)       & 1u) ? 0.f : ex2(c[nt][0] * EXP_SCALE))
                       + (((w0 >> (sh + 1)) & 1u) ? 0.f : ex2(c[nt][1] * EXP_SCALE));
                rsum1 += (((w1 >> sh)       & 1u) ? 0.f : ex2(c[nt][2] * EXP_SCALE))
                       + (((w1 >> (sh + 1)) & 1u) ? 0.f : ex2(c[nt][3] * EXP_SCALE));
            }
        }
        __syncthreads();
    }
    rsum0 += __shfl_xor_sync(0xffffffffu, rsum0, 1);
    rsum0 += __shfl_xor_sync(0xffffffffu, rsum0, 2);
    rsum1 += __shfl_xor_sync(0xffffffffu, rsum1, 1);
    rsum1 += __shfl_xor_sync(0xffffffffu, rsum1, 2);
    const float invl0 = 1.0f / rsum0;
    const float invl1 = 1.0f / rsum1;

    // -------- pass 2: 128-row K tiles + double-buffered V, tf32 scores ------
    float ctx[8][4];
    #pragma unroll
    for (int nt = 0; nt < 8; ++nt)
        #pragma unroll
        for (int q = 0; q < 4; ++q) ctx[nt][q] = 0.f;

    load_kv(0, 0);
    for (int jj = 0; jj < Sc; jj += 128) {
        const int cur = (jj >> 7) & 1;
        if (jj + 128 < Sc) { load_kv(jj + 128, cur ^ 1); cp_wait<1>(); }
        else               { cp_wait<0>(); }
        __syncthreads();
        float (*ksb)[68] = cur ? ks1 : ks0;

        #pragma unroll
        for (int sub = 0; sub < 2; ++sub) {
            const int jje = jj + sub * 64;
            float (*ks)[68] = ksb + sub * 64;
            __nv_bfloat16 (*vs)[72] =
                (__nv_bfloat16 (*)[72])(sbuf + 69632 + (cur * 2 + sub) * 9216);

            #pragma unroll
            for (int half = 0; half < 2; ++half) {
                float c[4][4];
                #pragma unroll
                for (int ntl = 0; ntl < 4; ++ntl)
                    #pragma unroll
                    for (int q = 0; q < 4; ++q) c[ntl][q] = 0.f;

                #pragma unroll
                for (int kf = 0; kf < 8; ++kf) {
                    const int k0 = kf * 8;
                    #pragma unroll
                    for (int ntl = 0; ntl < 4; ++ntl) {
                        const int n = (half * 4 + ntl) * 8 + g;
                        unsigned b0 = __float_as_uint(ks[n][k0 + t]);
                        unsigned b1 = __float_as_uint(ks[n][k0 + t + 4]);
                        mma_tf32(c[ntl][0], c[ntl][1], c[ntl][2], c[ntl][3],
                                 A[kf][0], A[kf][1], A[kf][2], A[kf][3], b0, b1);
                    }
                }

                const unsigned w0 = mp0[(jje >> 5) + half];
                const unsigned w1 = mp1[(jje >> 5) + half];

                unsigned pf[4][2];
                #pragma unroll
                for (int ntl = 0; ntl < 4; ++ntl) {
                    const int nt = half * 4 + ntl;
                    const int jl = nt * 8 + t * 2;
                    const int sh = jl & 31;
                    float p0 = ((w0 >> sh)       & 1u) ? 0.f : ex2(c[ntl][0] * EXP_SCALE) * invl0;
                    float p1 = ((w0 >> (sh + 1)) & 1u) ? 0.f : ex2(c[ntl][1] * EXP_SCALE) * invl0;
                    float p2 = ((w1 >> sh)       & 1u) ? 0.f : ex2(c[ntl][2] * EXP_SCALE) * invl1;
                    float p3 = ((w1 >> (sh + 1)) & 1u) ? 0.f : ex2(c[ntl][3] * EXP_SCALE) * invl1;
                    stcs2(arow0 + jje + jl, p0, p1);
                    stcs2(arow1 + jje + jl, p2, p3);
                    pf[ntl][0] = pack_bf16x2(p0, p1);
                    pf[ntl][1] = pack_bf16x2(p2, p3);
                }

                #pragma unroll
                for (int kfl = 0; kfl < 2; ++kfl) {
                    const int k0 = (half * 2 + kfl) * 16;
                    const unsigned a0 = pf[2 * kfl    ][0];
                    const unsigned a1 = pf[2 * kfl    ][1];
                    const unsigned a2 = pf[2 * kfl + 1][0];
                    const unsigned a3 = pf[2 * kfl + 1][1];
                    #pragma unroll
                    for (int q = 0; q < 4; ++q) {
                        const int nt0 = 2 * q;
                        unsigned r0, r1, r2, r3;
                        ldm_x4(r0, r1, r2, r3,
                               &vs[(nt0 + (lm >> 1)) * 8 + lr][k0 + (lm & 1) * 8]);
                        mma_bf16(ctx[nt0][0], ctx[nt0][1], ctx[nt0][2], ctx[nt0][3],
                                 a0, a1, a2, a3, r0, r1);
                        mma_bf16(ctx[nt0 + 1][0], ctx[nt0 + 1][1], ctx[nt0 + 1][2], ctx[nt0 + 1][3],
                                 a0, a1, a2, a3, r2, r3);
                    }
                }
            }
        }
        __syncthreads();
    }

    const int s = i0 + warp * 16 + g;
    const size_t crow0 = ((size_t)b * Sc + s)     * Dc;
    const size_t crow1 = ((size_t)b * Sc + s + 8) * Dc;
    #pragma unroll
    for (int nt = 0; nt < 8; ++nt) {
        const int col = h * DKc + nt * 8 + t * 2;
        *(__nv_bfloat162*)&g_ctxb[crow0 + col] = __floats2bfloat162_rn(ctx[nt][0], ctx[nt][1]);
        *(__nv_bfloat162*)&g_ctxb[crow1 + col] = __floats2bfloat162_rn(ctx[nt][2], ctx[nt][3]);
    }
}

// ---------------------------------------------------------------------------
// Kernel 3: output projection, bf16 MMA, cp.async 2-stage.
// ---------------------------------------------------------------------------
__global__ __launch_bounds__(256, 2) void oproj_mma_kernel(
    const float* __restrict__ bo, const float* __restrict__ Qres)
{
    const __nv_bfloat16* Wt = g_wT[3];

    __shared__ __align__(16) __nv_bfloat16 as[2][128][40];
    __shared__ __align__(16) __nv_bfloat16 bs[2][128][40];

    const int tid  = threadIdx.x;
    const int warp = tid >> 5, lane = tid & 31;
    const int g = lane >> 2, t = lane & 3;
    const int wm = warp >> 1, wn = warp & 1;
    const int row0 = blockIdx.y * 128;
    const int col0 = blockIdx.x * 128;

    float c[2][8][4];
    #pragma unroll
    for (int mt = 0; mt < 2; ++mt)
        #pragma unroll
        for (int nt = 0; nt < 8; ++nt)
            #pragma unroll
            for (int q = 0; q < 4; ++q) c[mt][nt][q] = 0.f;

    auto load_stage = [&](int kk, int st) {
        #pragma unroll
        for (int it = 0; it < 2; ++it) {
            int f = tid + it * 256;
            int r = f >> 2, c8 = (f & 3) * 8;
            cp16(&as[st][r][c8], g_ctxb + (size_t)(row0 + r) * Dc + kk + c8);
            cp16(&bs[st][r][c8], Wt     + (size_t)(col0 + r) * Dc + kk + c8);
        }
        cp_commit();
    };

    load_stage(0, 0);

    const int nT = Dc / 32;
    for (int tt = 0; tt < nT; ++tt) {
        const int cur = tt & 1;
        if (tt + 1 < nT) { load_stage((tt + 1) * 32, cur ^ 1); cp_wait<1>(); }
        else             { cp_wait<0>(); }
        __syncthreads();

        #pragma unroll
        for (int kf = 0; kf < 2; ++kf) {
            const int k0 = kf * 16;
            unsigned A[2][4];
            #pragma unroll
            for (int mt = 0; mt < 2; ++mt) {
                int r = wm * 32 + mt * 16 + g;
                A[mt][0] = *(const unsigned*)&as[cur][r    ][k0     + t * 2];
                A[mt][1] = *(const unsigned*)&as[cur][r + 8][k0     + t * 2];
                A[mt][2] = *(const unsigned*)&as[cur][r    ][k0 + 8 + t * 2];
                A[mt][3] = *(const unsigned*)&as[cur][r + 8][k0 + 8 + t * 2];
            }
            #pragma unroll
            for (int nt = 0; nt < 8; ++nt) {
                int n = wn * 64 + nt * 8 + g;
                unsigned b0 = *(const unsigned*)&bs[cur][n][k0     + t * 2];
                unsigned b1 = *(const unsigned*)&bs[cur][n][k0 + 8 + t * 2];
                mma_bf16(c[0][nt][0], c[0][nt][1], c[0][nt][2], c[0][nt][3],
                         A[0][0], A[0][1], A[0][2], A[0][3], b0, b1);
                mma_bf16(c[1][nt][0], c[1][nt][1], c[1][nt][2], c[1][nt][3],
                         A[1][0], A[1][1], A[1][2], A[1][3], b0, b1);
            }
        }
        __syncthreads();
    }

    #pragma unroll
    for (int mt = 0; mt < 2; ++mt) {
        #pragma unroll
        for (int nt = 0; nt < 8; ++nt) {
            const int col = col0 + wn * 64 + nt * 8 + t * 2;
            const float bi0 = bo[col], bi1 = bo[col + 1];
            const int r0 = row0 + wm * 32 + mt * 16 + g;
            #pragma unroll
            for (int rr = 0; rr < 2; ++rr) {
                const int rowg = r0 + rr * 8;
                const float* res = Qres + (size_t)rowg * Dc + col;
                float2 rv = *(const float2*)res;
                float2 o = make_float2(c[mt][nt][rr * 2 + 0] + bi0 + rv.x,
                                       c[mt][nt][rr * 2 + 1] + bi1 + rv.y);
                *(float2*)(g_y + (size_t)rowg * Dc + col) = o;
            }
        }
    }
}

// ---------------------------------------------------------------------------
// Kernel 4: LayerNorm per row (fp32).
// ---------------------------------------------------------------------------
__global__ __launch_bounds__(256) void ln_kernel(
    const float* __restrict__ gamma, const float* __restrict__ beta,
    float* __restrict__ out)
{
    const int row = blockIdx.x;
    const int tid = threadIdx.x;
    const float* y = g_y + (size_t)row * Dc;

    float4 v = ((const float4*)y)[tid];
    float s  = v.x + v.y + v.z + v.w;
    float q  = v.x * v.x + v.y * v.y + v.z * v.z + v.w * v.w;

    __shared__ float ss[8];
    __shared__ float sq[8];
    #pragma unroll
    for (int o = 16; o > 0; o >>= 1) {
        s += __shfl_xor_sync(0xffffffffu, s, o);
        q += __shfl_xor_sync(0xffffffffu, q, o);
    }
    if ((tid & 31) == 0) { ss[tid >> 5] = s; sq[tid >> 5] = q; }
    __syncthreads();
    s = ss[tid & 7];
    q = sq[tid & 7];
    #pragma unroll
    for (int o = 4; o > 0; o >>= 1) {
        s += __shfl_xor_sync(0xffffffffu, s, o);
        q += __shfl_xor_sync(0xffffffffu, q, o);
    }

    const float mu  = s * (1.0f / Dc);
    const float var = q * (1.0f / Dc) - mu * mu;
    const float inv = rsqrtf(var + 1e-5f);

    float4 gv = ((const float4*)gamma)[tid];
    float4 bv = ((const float4*)beta)[tid];
    float4 o4 = make_float4((v.x - mu) * inv * gv.x + bv.x,
                            (v.y - mu) * inv * gv.y + bv.y,
                            (v.z - mu) * inv * gv.z + bv.z,
                            (v.w - mu) * inv * gv.w + bv.w);
    ((float4*)(out + (size_t)row * Dc))[tid] = o4;
}

// ---------------------------------------------------------------------------
// Launch
// ---------------------------------------------------------------------------
extern "C" void kernel_launch(void* const* d_in, const int* in_sizes, int n_in,
                              void* d_out, int out_size)
{
    const float* Qin  = (const float*)d_in[0];
    const unsigned* mask = (const unsigned*)d_in[3];
    const float* Wq = (const float*)d_in[4];
    const float* bq = (const float*)d_in[5];
    const float* Wk = (const float*)d_in[6];
    const float* bk = (const float*)d_in[7];
    const float* Wv = (const float*)d_in[8];
    const float* bv = (const float*)d_in[9];
    const float* Wo = (const float*)d_in[10];
    const float* bo = (const float*)d_in[11];
    const float* ln_g = (const float*)d_in[12];
    const float* ln_b = (const float*)d_in[13];

    float* out  = (float*)d_out;
    float* attn = out + (size_t)Bc * Sc * Dc;

    static bool attr_done = false;
    if (!attr_done) {
        cudaFuncSetAttribute(attn_fused_kernel,
                             cudaFuncAttributeMaxDynamicSharedMemorySize, ATTN_SMEM);
        attr_done = true;
    }

    pre_kernel       <<<10240, 256>>>(Qin, mask, Wq, Wk, Wv, Wo);
    proj_all_kernel  <<<dim3(Dc / 128, Mc / 128, 3), 256>>>(bq, bk, bv);
    attn_fused_kernel<<<dim3(Sc / 128, BHc), 256, ATTN_SMEM>>>(attn);
    oproj_mma_kernel <<<dim3(Dc / 128, Mc / 128), 256>>>(bo, Qin);
    ln_kernel        <<<Mc, 256>>>(ln_g, ln_b, out);
}

// round 16
// speedup vs baseline: 1.0424x; 1.0424x over previous
#include <cuda_runtime.h>
#include <cuda_bf16.h>

#define Bc   2
#define Sc   2048
#define Dc   1024
#define Hc   16
#define DKc  64
#define Mc   (Bc * Sc)        // 4096
#define BHc  (Bc * Hc)        // 32

// exp(0.125*x) == 2^(x * 0.125*log2(e))
#define EXP_SCALE 0.18033688011112042f

// ---------------------------------------------------------------------------
// Scratch (__device__ globals; no cudaMalloc allowed)
// ---------------------------------------------------------------------------
__device__ __align__(16) __nv_bfloat16 g_xb [(size_t)Mc * Dc];          // X bf16 (V path)
__device__ __align__(16) float         g_xtf[(size_t)Mc * Dc];          // X tf32-rounded (QK path)
__device__ __align__(16) __nv_bfloat16 g_wT [4][(size_t)Dc * Dc];       // bf16 W^T ([2],[3] used)
__device__ __align__(16) float         g_wTf[2][(size_t)Dc * Dc];       // tf32-rounded W^T (Wq,Wk)
__device__ __align__(16) float         g_qf [(size_t)BHc * Sc * DKc];   // q tf32-rounded [bh][s][dk]
__device__ __align__(16) float         g_kf [(size_t)BHc * Sc * DKc];   // k tf32-rounded [bh][s][dk]
__device__ __align__(16) __nv_bfloat16 g_kb [(size_t)BHc * Sc * DKc];   // k bf16 (pass-1 sums)
__device__ __align__(16) __nv_bfloat16 g_vT [(size_t)BHc * DKc * Sc];   // v bf16 [bh][dk][s]
__device__ __align__(16) __nv_bfloat16 g_ctxb[(size_t)Mc * Dc];         // ctx bf16
__device__ unsigned g_mask[(size_t)Bc * Sc * (Sc / 32)];                 // bit-packed mask
__device__ __align__(16) float g_y [(size_t)Mc * Dc];                    // pre-LN

// ---------------------------------------------------------------------------
// MMA + async-copy + ldmatrix helpers
// ---------------------------------------------------------------------------
__device__ __forceinline__ void mma_bf16(
    float& c0, float& c1, float& c2, float& c3,
    unsigned a0, unsigned a1, unsigned a2, unsigned a3,
    unsigned b0, unsigned b1)
{
    asm volatile(
        "mma.sync.aligned.m16n8k16.row.col.f32.bf16.bf16.f32 "
        "{%0,%1,%2,%3}, {%4,%5,%6,%7}, {%8,%9}, {%0,%1,%2,%3};\n"
        : "+f"(c0), "+f"(c1), "+f"(c2), "+f"(c3)
        : "r"(a0), "r"(a1), "r"(a2), "r"(a3), "r"(b0), "r"(b1));
}

__device__ __forceinline__ void mma_tf32(
    float& c0, float& c1, float& c2, float& c3,
    unsigned a0, unsigned a1, unsigned a2, unsigned a3,
    unsigned b0, unsigned b1)
{
    asm volatile(
        "mma.sync.aligned.m16n8k8.row.col.f32.tf32.tf32.f32 "
        "{%0,%1,%2,%3}, {%4,%5,%6,%7}, {%8,%9}, {%0,%1,%2,%3};\n"
        : "+f"(c0), "+f"(c1), "+f"(c2), "+f"(c3)
        : "r"(a0), "r"(a1), "r"(a2), "r"(a3), "r"(b0), "r"(b1));
}

__device__ __forceinline__ float f2tf_f(float x)
{
    unsigned r;
    asm("cvt.rna.tf32.f32 %0, %1;" : "=r"(r) : "f"(x));
    return __uint_as_float(r);
}

__device__ __forceinline__ unsigned pack_bf16x2(float a, float b)
{
    unsigned r;
    asm("cvt.rn.bf16x2.f32 %0, %1, %2;" : "=r"(r) : "f"(b), "f"(a));
    return r;
}

__device__ __forceinline__ float ex2(float x)
{
    float r;
    asm("ex2.approx.f32 %0, %1;" : "=f"(r) : "f"(x));
    return r;
}

__device__ __forceinline__ void cp16(void* smem, const void* gmem)
{
    unsigned sa = (unsigned)__cvta_generic_to_shared(smem);
    asm volatile("cp.async.cg.shared.global [%0], [%1], 16;\n"
                 :: "r"(sa), "l"(gmem));
}
__device__ __forceinline__ void cp_commit()
{
    asm volatile("cp.async.commit_group;\n");
}
template<int N> __device__ __forceinline__ void cp_wait()
{
    asm volatile("cp.async.wait_group %0;\n" :: "n"(N));
}

__device__ __forceinline__ void ldm_x4(unsigned& r0, unsigned& r1,
                                       unsigned& r2, unsigned& r3, const void* p)
{
    unsigned a = (unsigned)__cvta_generic_to_shared(p);
    asm volatile("ldmatrix.sync.aligned.m8n8.x4.shared.b16 {%0,%1,%2,%3}, [%4];\n"
                 : "=r"(r0), "=r"(r1), "=r"(r2), "=r"(r3) : "r"(a));
}

__device__ __forceinline__ void stcs2(float* p, float a, float b)
{
    asm volatile("st.global.cs.v2.f32 [%0], {%1, %2};\n"
                 :: "l"(p), "f"(a), "f"(b) : "memory");
}

// ---------------------------------------------------------------------------
// Kernel 0: merged pre-pass.
//   blocks [0,4096):        X -> bf16 + tf32
//   blocks [4096,8192):     W transpose (z = idx>>10)
//   blocks [8192,10240):    mask bit-pack (128 words per block)
// ---------------------------------------------------------------------------
__global__ __launch_bounds__(256) void pre_kernel(
    const float* __restrict__ X, const unsigned* __restrict__ mask,
    const float* __restrict__ W0, const float* __restrict__ W1,
    const float* __restrict__ W2, const float* __restrict__ W3)
{
    __shared__ float tile[32][33];
    const int bid = blockIdx.x;
    const int tid = threadIdx.x;

    if (bid < 4096) {
        size_t i = ((size_t)bid * 256 + tid) * 4;
        float4 v = *(const float4*)(X + i);
        __nv_bfloat162* d = (__nv_bfloat162*)(g_xb + i);
        d[0] = __floats2bfloat162_rn(v.x, v.y);
        d[1] = __floats2bfloat162_rn(v.z, v.w);
        float4 tv = make_float4(f2tf_f(v.x), f2tf_f(v.y), f2tf_f(v.z), f2tf_f(v.w));
        *(float4*)(g_xtf + i) = tv;
    } else if (bid < 8192) {
        const int wb = bid - 4096;
        const int z  = wb >> 10;
        const int li = wb & 1023;
        const float* W = z == 0 ? W0 : z == 1 ? W1 : z == 2 ? W2 : W3;
        const int tx = tid & 31, ty = tid >> 5;
        const int k0 = (li & 31) * 32, n0 = (li >> 5) * 32;
        #pragma unroll
        for (int i = 0; i < 4; ++i)
            tile[ty + i * 8][tx] = W[(size_t)(k0 + ty + i * 8) * Dc + n0 + tx];
        __syncthreads();
        if (z < 2) {
            float* out = g_wTf[z];
            #pragma unroll
            for (int i = 0; i < 4; ++i)
                out[(size_t)(n0 + ty + i * 8) * Dc + k0 + tx] =
                    f2tf_f(tile[tx][ty + i * 8]);
        } else {
            __nv_bfloat16* out = g_wT[z];
            #pragma unroll
            for (int i = 0; i < 4; ++i)
                out[(size_t)(n0 + ty + i * 8) * Dc + k0 + tx] =
                    __float2bfloat16(tile[tx][ty + i * 8]);
        }
    } else {
        const int mb   = bid - 8192;           // 0..2047, 128 words each
        const int warp = tid >> 5, lane = tid & 31;
        const int wbase = mb * 128 + warp * 16;
        #pragma unroll
        for (int k = 0; k < 16; ++k) {
            const int w = wbase + k;
            unsigned v = mask[(size_t)w * 32 + lane];
            unsigned bits = __ballot_sync(0xffffffffu, v != 0);
            if (lane == 0) g_mask[w] = bits;
        }
    }
}

// ---------------------------------------------------------------------------
// Kernel 1: ALL projections in one launch (z in blockIdx.z).
//   z=0: q (tf32, BK=16), z=1: k (tf32, + bf16 copy), z=2: v (bf16, BK=32).
// ---------------------------------------------------------------------------
__global__ __launch_bounds__(256, 2) void proj_all_kernel(
    const float* __restrict__ bq, const float* __restrict__ bk,
    const float* __restrict__ bv)
{
    __shared__ __align__(16) unsigned char smA[20480];
    __shared__ __align__(16) unsigned char smB[20480];

    const int z    = blockIdx.z;
    const int tid  = threadIdx.x;
    const int warp = tid >> 5, lane = tid & 31;
    const int g = lane >> 2, t = lane & 3;
    const int wm = warp >> 1, wn = warp & 1;
    const int row0 = blockIdx.y * 128;
    const int col0 = blockIdx.x * 128;

    float c[2][8][4];
    #pragma unroll
    for (int mt = 0; mt < 2; ++mt)
        #pragma unroll
        for (int nt = 0; nt < 8; ++nt)
            #pragma unroll
            for (int q = 0; q < 4; ++q) c[mt][nt][q] = 0.f;

    if (z < 2) {
        const float* Wt   = g_wTf[z];
        const float* bias = z == 0 ? bq : bk;
        float* outp = z == 0 ? g_qf : g_kf;

        float (*as)[128][20] = (float (*)[128][20])smA;
        float (*bs)[128][20] = (float (*)[128][20])smB;

        auto load_stage = [&](int kk, int st) {
            #pragma unroll
            for (int it = 0; it < 2; ++it) {
                int f = tid + it * 256;
                int r = f >> 2, c4 = (f & 3) * 4;
                cp16(&as[st][r][c4], g_xtf + (size_t)(row0 + r) * Dc + kk + c4);
                cp16(&bs[st][r][c4], Wt    + (size_t)(col0 + r) * Dc + kk + c4);
            }
            cp_commit();
        };

        load_stage(0, 0);
        const int nT = Dc / 16;
        for (int tt = 0; tt < nT; ++tt) {
            const int cur = tt & 1;
            if (tt + 1 < nT) { load_stage((tt + 1) * 16, cur ^ 1); cp_wait<1>(); }
            else             { cp_wait<0>(); }
            __syncthreads();

            #pragma unroll
            for (int kf = 0; kf < 2; ++kf) {
                const int k0 = kf * 8;
                unsigned A[2][4];
                #pragma unroll
                for (int mt = 0; mt < 2; ++mt) {
                    int r = wm * 32 + mt * 16 + g;
                    A[mt][0] = __float_as_uint(as[cur][r    ][k0 + t]);
                    A[mt][1] = __float_as_uint(as[cur][r + 8][k0 + t]);
                    A[mt][2] = __float_as_uint(as[cur][r    ][k0 + t + 4]);
                    A[mt][3] = __float_as_uint(as[cur][r + 8][k0 + t + 4]);
                }
                #pragma unroll
                for (int nt = 0; nt < 8; ++nt) {
                    int n = wn * 64 + nt * 8 + g;
                    unsigned b0 = __float_as_uint(bs[cur][n][k0 + t]);
                    unsigned b1 = __float_as_uint(bs[cur][n][k0 + t + 4]);
                    mma_tf32(c[0][nt][0], c[0][nt][1], c[0][nt][2], c[0][nt][3],
                             A[0][0], A[0][1], A[0][2], A[0][3], b0, b1);
                    mma_tf32(c[1][nt][0], c[1][nt][1], c[1][nt][2], c[1][nt][3],
                             A[1][0], A[1][1], A[1][2], A[1][3], b0, b1);
                }
            }
            __syncthreads();
        }

        #pragma unroll
        for (int mt = 0; mt < 2; ++mt) {
            #pragma unroll
            for (int nt = 0; nt < 8; ++nt) {
                const int col = col0 + wn * 64 + nt * 8 + t * 2;
                const int h = col >> 6, dk = col & 63;
                const float bi0 = bias[col], bi1 = bias[col + 1];
                const int r0 = row0 + wm * 32 + mt * 16 + g;
                #pragma unroll
                for (int rr = 0; rr < 2; ++rr) {
                    const int rowg = r0 + rr * 8;
                    const int b = rowg >> 11, s = rowg & 2047;
                    const float v0 = c[mt][nt][rr * 2 + 0] + bi0;
                    const float v1 = c[mt][nt][rr * 2 + 1] + bi1;
                    const size_t off = ((size_t)(b * Hc + h) * Sc + s) * DKc + dk;
                    *(float2*)(outp + off) = make_float2(f2tf_f(v0), f2tf_f(v1));
                    if (z == 1)
                        *(__nv_bfloat162*)(g_kb + off) = __floats2bfloat162_rn(v0, v1);
                }
            }
        }
    } else {
        const __nv_bfloat16* Wt = g_wT[2];

        __nv_bfloat16 (*as)[128][40] = (__nv_bfloat16 (*)[128][40])smA;
        __nv_bfloat16 (*bs)[128][40] = (__nv_bfloat16 (*)[128][40])smB;

        auto load_stage = [&](int kk, int st) {
            #pragma unroll
            for (int it = 0; it < 2; ++it) {
                int f = tid + it * 256;
                int r = f >> 2, c8 = (f & 3) * 8;
                cp16(&as[st][r][c8], g_xb + (size_t)(row0 + r) * Dc + kk + c8);
                cp16(&bs[st][r][c8], Wt   + (size_t)(col0 + r) * Dc + kk + c8);
            }
            cp_commit();
        };

        load_stage(0, 0);
        const int nT = Dc / 32;
        for (int tt = 0; tt < nT; ++tt) {
            const int cur = tt & 1;
            if (tt + 1 < nT) { load_stage((tt + 1) * 32, cur ^ 1); cp_wait<1>(); }
            else             { cp_wait<0>(); }
            __syncthreads();

            #pragma unroll
            for (int kf = 0; kf < 2; ++kf) {
                const int k0 = kf * 16;
                unsigned A[2][4];
                #pragma unroll
                for (int mt = 0; mt < 2; ++mt) {
                    int r = wm * 32 + mt * 16 + g;
                    A[mt][0] = *(const unsigned*)&as[cur][r    ][k0     + t * 2];
                    A[mt][1] = *(const unsigned*)&as[cur][r + 8][k0     + t * 2];
                    A[mt][2] = *(const unsigned*)&as[cur][r    ][k0 + 8 + t * 2];
                    A[mt][3] = *(const unsigned*)&as[cur][r + 8][k0 + 8 + t * 2];
                }
                #pragma unroll
                for (int nt = 0; nt < 8; ++nt) {
                    int n = wn * 64 + nt * 8 + g;
                    unsigned b0 = *(const unsigned*)&bs[cur][n][k0     + t * 2];
                    unsigned b1 = *(const unsigned*)&bs[cur][n][k0 + 8 + t * 2];
                    mma_bf16(c[0][nt][0], c[0][nt][1], c[0][nt][2], c[0][nt][3],
                             A[0][0], A[0][1], A[0][2], A[0][3], b0, b1);
                    mma_bf16(c[1][nt][0], c[1][nt][1], c[1][nt][2], c[1][nt][3],
                             A[1][0], A[1][1], A[1][2], A[1][3], b0, b1);
                }
            }
            __syncthreads();
        }

        #pragma unroll
        for (int mt = 0; mt < 2; ++mt) {
            #pragma unroll
            for (int nt = 0; nt < 8; ++nt) {
                const int col = col0 + wn * 64 + nt * 8 + t * 2;
                const int h = col >> 6, dk = col & 63;
                const float bi0 = bv[col], bi1 = bv[col + 1];
                const int r0 = row0 + wm * 32 + mt * 16 + g;
                #pragma unroll
                for (int rr = 0; rr < 2; ++rr) {
                    const int rowg = r0 + rr * 8;
                    const int b = rowg >> 11, s = rowg & 2047;
                    g_vT[((size_t)(b * Hc + h) * DKc + dk    ) * Sc + s] =
                        __float2bfloat16(c[mt][nt][rr * 2 + 0] + bi0);
                    g_vT[((size_t)(b * Hc + h) * DKc + dk + 1) * Sc + s] =
                        __float2bfloat16(c[mt][nt][rr * 2 + 1] + bi1);
                }
            }
        }
    }
}

// ---------------------------------------------------------------------------
// Kernel 2: FUSED attention, static smem, 2 blocks/SM.
//   pass 1: bf16 q.k^T on 128-row K tiles (ldmatrix B) -> masked-exp row sums.
//   pass 2: tf32 q.k^T on 64-row K tiles -> p = e/l, streaming-store p,
//           C-frags -> bf16 A-frags of p @ V (ldmatrix V).
// ---------------------------------------------------------------------------
__global__ __launch_bounds__(256, 2) void attn_fused_kernel(float* __restrict__ attn)
{
    const int bh = blockIdx.y;
    const int i0 = blockIdx.x * 128;
    const int b  = bh >> 4, h = bh & 15;

    // unions: setup qs f32[128][68] (34816B)
    //   pass1: kb[2][128][72] bf16 @0 / @18432 (36864B)
    //   pass2: ks0 f32[64][68] @0, ks1 @17408, vs bf16[64][72] @34816
    __shared__ __align__(16) unsigned char sbuf[44032];
    float (*qs)[68] = (float (*)[68])sbuf;
    __nv_bfloat16 (*kb0)[72] = (__nv_bfloat16 (*)[72])sbuf;
    __nv_bfloat16 (*kb1)[72] = (__nv_bfloat16 (*)[72])(sbuf + 18432);
    float (*ks0)[68] = (float (*)[68])sbuf;
    float (*ks1)[68] = (float (*)[68])(sbuf + 17408);
    __nv_bfloat16 (*vs)[72] = (__nv_bfloat16 (*)[72])(sbuf + 34816);

    const int tid = threadIdx.x, warp = tid >> 5, lane = tid & 31;
    const int g = lane >> 2, t = lane & 3;
    const int lm = lane >> 3, lr = lane & 7;

    const float* qbase = g_qf + ((size_t)bh * Sc + i0) * DKc;
    const float* kbase = g_kf + (size_t)bh * Sc * DKc;
    const __nv_bfloat16* kbbase = g_kb + (size_t)bh * Sc * DKc;
    const __nv_bfloat16* vbase  = g_vT + (size_t)bh * DKc * Sc;

    #pragma unroll
    for (int it = 0; it < 8; ++it) {
        int f = tid + it * 256;
        int r = f >> 4, c4 = (f & 15) * 4;
        *(float4*)&qs[r][c4] = *(const float4*)(qbase + (size_t)r * DKc + c4);
    }
    __syncthreads();

    unsigned A[8][4];    // tf32 fragments (pass 2)
    unsigned Ab[4][4];   // bf16 fragments (pass 1)
    {
        const int r = warp * 16 + g;
        #pragma unroll
        for (int kf = 0; kf < 8; ++kf) {
            const int k0 = kf * 8;
            A[kf][0] = __float_as_uint(qs[r    ][k0 + t]);
            A[kf][1] = __float_as_uint(qs[r + 8][k0 + t]);
            A[kf][2] = __float_as_uint(qs[r    ][k0 + t + 4]);
            A[kf][3] = __float_as_uint(qs[r + 8][k0 + t + 4]);
        }
        #pragma unroll
        for (int kf = 0; kf < 4; ++kf) {
            const int k0 = kf * 16;
            Ab[kf][0] = pack_bf16x2(qs[r    ][k0     + t * 2], qs[r    ][k0     + t * 2 + 1]);
            Ab[kf][1] = pack_bf16x2(qs[r + 8][k0     + t * 2], qs[r + 8][k0     + t * 2 + 1]);
            Ab[kf][2] = pack_bf16x2(qs[r    ][k0 + 8 + t * 2], qs[r    ][k0 + 8 + t * 2 + 1]);
            Ab[kf][3] = pack_bf16x2(qs[r + 8][k0 + 8 + t * 2], qs[r + 8][k0 + 8 + t * 2 + 1]);
        }
    }
    __syncthreads();

    const int ig0 = i0 + warp * 16 + g;
    const int ig1 = ig0 + 8;
    const unsigned* mp0 = g_mask + ((size_t)b * Sc + ig0) * (Sc / 32);
    const unsigned* mp1 = g_mask + ((size_t)b * Sc + ig1) * (Sc / 32);
    float* arow0 = attn + ((size_t)bh * Sc + ig0) * Sc;
    float* arow1 = attn + ((size_t)bh * Sc + ig1) * Sc;

    auto load_kb128 = [&](int jj, int st) {   // 128 rows of bf16 K
        __nv_bfloat16 (*dst)[72] = st ? kb1 : kb0;
        #pragma unroll
        for (int it = 0; it < 4; ++it) {
            int f = tid + it * 256;
            int r = f >> 3, c8 = (f & 7) * 8;
            cp16(&dst[r][c8], kbbase + (size_t)(jj + r) * DKc + c8);
        }
        cp_commit();
    };
    auto load_k = [&](int jj, int st) {
        float (*dst)[68] = st ? ks1 : ks0;
        #pragma unroll
        for (int it = 0; it < 4; ++it) {
            int f = tid + it * 256;
            int r = f >> 4, c4 = (f & 15) * 4;
            cp16(&dst[r][c4], kbase + (size_t)(jj + r) * DKc + c4);
        }
        cp_commit();
    };
    auto load_v = [&](int jj) {
        #pragma unroll
        for (int it = 0; it < 2; ++it) {
            int f = tid + it * 256;
            int dk = f >> 3, c8 = (f & 7) * 8;
            cp16(&vs[dk][c8], vbase + (size_t)dk * Sc + jj + c8);
        }
        cp_commit();
    };

    // ---------------- pass 1: row sums (bf16 MMA, 128-row tiles) ------------
    float rsum0 = 0.f, rsum1 = 0.f;
    load_kb128(0, 0);
    for (int jj = 0; jj < Sc; jj += 128) {
        const int cur = (jj >> 7) & 1;
        if (jj + 128 < Sc) { load_kb128(jj + 128, cur ^ 1); cp_wait<1>(); }
        else               { cp_wait<0>(); }
        __syncthreads();
        __nv_bfloat16 (*kb)[72] = cur ? kb1 : kb0;

        #pragma unroll
        for (int sub = 0; sub < 2; ++sub) {
            const int jje = jj + sub * 64;
            __nv_bfloat16 (*kbs)[72] = (__nv_bfloat16 (*)[72])(kb + sub * 64);

            float c[8][4];
            #pragma unroll
            for (int nt = 0; nt < 8; ++nt)
                #pragma unroll
                for (int q = 0; q < 4; ++q) c[nt][q] = 0.f;
            #pragma unroll
            for (int kf = 0; kf < 4; ++kf) {
                const int k0 = kf * 16;
                #pragma unroll
                for (int q = 0; q < 4; ++q) {
                    const int nt0 = 2 * q;
                    unsigned r0, r1, r2, r3;
                    ldm_x4(r0, r1, r2, r3,
                           &kbs[(nt0 + (lm >> 1)) * 8 + lr][k0 + (lm & 1) * 8]);
                    mma_bf16(c[nt0][0], c[nt0][1], c[nt0][2], c[nt0][3],
                             Ab[kf][0], Ab[kf][1], Ab[kf][2], Ab[kf][3], r0, r1);
                    mma_bf16(c[nt0 + 1][0], c[nt0 + 1][1], c[nt0 + 1][2], c[nt0 + 1][3],
                             Ab[kf][0], Ab[kf][1], Ab[kf][2], Ab[kf][3], r2, r3);
                }
            }

            const unsigned m00 = mp0[jje >> 5], m01 = mp0[(jje >> 5) + 1];
            const unsigned m10 = mp1[jje >> 5], m11 = mp1[(jje >> 5) + 1];
            #pragma unroll
            for (int nt = 0; nt < 8; ++nt) {
                const int jl = nt * 8 + t * 2;
                const unsigned w0 = (jl & 32) ? m01 : m00;
                const unsigned w1 = (jl & 32) ? m11 : m10;
                const int sh = jl & 31;
                rsum0 += (((w0 >> sh)       & 1u) ? 0.f : ex2(c[nt][0] * EXP_SCALE))
                       + (((w0 >> (sh + 1)) & 1u) ? 0.f : ex2(c[nt][1] * EXP_SCALE));
                rsum1 += (((w1 >> sh)       & 1u) ? 0.f : ex2(c[nt][2] * EXP_SCALE))
                       + (((w1 >> (sh + 1)) & 1u) ? 0.f : ex2(c[nt][3] * EXP_SCALE));
            }
        }
        __syncthreads();
    }
    rsum0 += __shfl_xor_sync(0xffffffffu, rsum0, 1);
    rsum0 += __shfl_xor_sync(0xffffffffu, rsum0, 2);
    rsum1 += __shfl_xor_sync(0xffffffffu, rsum1, 1);
    rsum1 += __shfl_xor_sync(0xffffffffu, rsum1, 2);
    const float invl0 = 1.0f / rsum0;
    const float invl1 = 1.0f / rsum1;

    // ---------------- pass 2: write p, ctx = p @ V (tf32 scores) ----------
    float ctx[8][4];
    #pragma unroll
    for (int nt = 0; nt < 8; ++nt)
        #pragma unroll
        for (int q = 0; q < 4; ++q) ctx[nt][q] = 0.f;

    load_k(0, 0);
    for (int jj = 0; jj < Sc; jj += 64) {
        const int cur = (jj >> 6) & 1;
        load_v(jj);
        if (jj + 64 < Sc) { load_k(jj + 64, cur ^ 1); cp_wait<1>(); }
        else              { cp_wait<0>(); }
        __syncthreads();
        float (*ks)[68] = cur ? ks1 : ks0;

        #pragma unroll
        for (int half = 0; half < 2; ++half) {
            float c[4][4];
            #pragma unroll
            for (int ntl = 0; ntl < 4; ++ntl)
                #pragma unroll
                for (int q = 0; q < 4; ++q) c[ntl][q] = 0.f;

            #pragma unroll
            for (int kf = 0; kf < 8; ++kf) {
                const int k0 = kf * 8;
                #pragma unroll
                for (int ntl = 0; ntl < 4; ++ntl) {
                    const int n = (half * 4 + ntl) * 8 + g;
                    unsigned b0 = __float_as_uint(ks[n][k0 + t]);
                    unsigned b1 = __float_as_uint(ks[n][k0 + t + 4]);
                    mma_tf32(c[ntl][0], c[ntl][1], c[ntl][2], c[ntl][3],
                             A[kf][0], A[kf][1], A[kf][2], A[kf][3], b0, b1);
                }
            }

            const unsigned w0 = mp0[(jj >> 5) + half];
            const unsigned w1 = mp1[(jj >> 5) + half];

            unsigned pf[4][2];
            #pragma unroll
            for (int ntl = 0; ntl < 4; ++ntl) {
                const int nt = half * 4 + ntl;
                const int jl = nt * 8 + t * 2;
                const int sh = jl & 31;
                float p0 = ((w0 >> sh)       & 1u) ? 0.f : ex2(c[ntl][0] * EXP_SCALE) * invl0;
                float p1 = ((w0 >> (sh + 1)) & 1u) ? 0.f : ex2(c[ntl][1] * EXP_SCALE) * invl0;
                float p2 = ((w1 >> sh)       & 1u) ? 0.f : ex2(c[ntl][2] * EXP_SCALE) * invl1;
                float p3 = ((w1 >> (sh + 1)) & 1u) ? 0.f : ex2(c[ntl][3] * EXP_SCALE) * invl1;
                stcs2(arow0 + jj + jl, p0, p1);
                stcs2(arow1 + jj + jl, p2, p3);
                pf[ntl][0] = pack_bf16x2(p0, p1);
                pf[ntl][1] = pack_bf16x2(p2, p3);
            }

            #pragma unroll
            for (int kfl = 0; kfl < 2; ++kfl) {
                const int k0 = (half * 2 + kfl) * 16;
                const unsigned a0 = pf[2 * kfl    ][0];
                const unsigned a1 = pf[2 * kfl    ][1];
                const unsigned a2 = pf[2 * kfl + 1][0];
                const unsigned a3 = pf[2 * kfl + 1][1];
                #pragma unroll
                for (int q = 0; q < 4; ++q) {
                    const int nt0 = 2 * q;
                    unsigned r0, r1, r2, r3;
                    ldm_x4(r0, r1, r2, r3,
                           &vs[(nt0 + (lm >> 1)) * 8 + lr][k0 + (lm & 1) * 8]);
                    mma_bf16(ctx[nt0][0], ctx[nt0][1], ctx[nt0][2], ctx[nt0][3],
                             a0, a1, a2, a3, r0, r1);
                    mma_bf16(ctx[nt0 + 1][0], ctx[nt0 + 1][1], ctx[nt0 + 1][2], ctx[nt0 + 1][3],
                             a0, a1, a2, a3, r2, r3);
                }
            }
        }
        __syncthreads();
    }

    const int s = i0 + warp * 16 + g;
    const size_t crow0 = ((size_t)b * Sc + s)     * Dc;
    const size_t crow1 = ((size_t)b * Sc + s + 8) * Dc;
    #pragma unroll
    for (int nt = 0; nt < 8; ++nt) {
        const int col = h * DKc + nt * 8 + t * 2;
        *(__nv_bfloat162*)&g_ctxb[crow0 + col] = __floats2bfloat162_rn(ctx[nt][0], ctx[nt][1]);
        *(__nv_bfloat162*)&g_ctxb[crow1 + col] = __floats2bfloat162_rn(ctx[nt][2], ctx[nt][3]);
    }
}

// ---------------------------------------------------------------------------
// Kernel 3: output projection, bf16 MMA, cp.async 2-stage.
// ---------------------------------------------------------------------------
__global__ __launch_bounds__(256, 2) void oproj_mma_kernel(
    const float* __restrict__ bo, const float* __restrict__ Qres)
{
    const __nv_bfloat16* Wt = g_wT[3];

    __shared__ __align__(16) __nv_bfloat16 as[2][128][40];
    __shared__ __align__(16) __nv_bfloat16 bs[2][128][40];

    const int tid  = threadIdx.x;
    const int warp = tid >> 5, lane = tid & 31;
    const int g = lane >> 2, t = lane & 3;
    const int wm = warp >> 1, wn = warp & 1;
    const int row0 = blockIdx.y * 128;
    const int col0 = blockIdx.x * 128;

    float c[2][8][4];
    #pragma unroll
    for (int mt = 0; mt < 2; ++mt)
        #pragma unroll
        for (int nt = 0; nt < 8; ++nt)
            #pragma unroll
            for (int q = 0; q < 4; ++q) c[mt][nt][q] = 0.f;

    auto load_stage = [&](int kk, int st) {
        #pragma unroll
        for (int it = 0; it < 2; ++it) {
            int f = tid + it * 256;
            int r = f >> 2, c8 = (f & 3) * 8;
            cp16(&as[st][r][c8], g_ctxb + (size_t)(row0 + r) * Dc + kk + c8);
            cp16(&bs[st][r][c8], Wt     + (size_t)(col0 + r) * Dc + kk + c8);
        }
        cp_commit();
    };

    load_stage(0, 0);

    const int nT = Dc / 32;
    for (int tt = 0; tt < nT; ++tt) {
        const int cur = tt & 1;
        if (tt + 1 < nT) { load_stage((tt + 1) * 32, cur ^ 1); cp_wait<1>(); }
        else             { cp_wait<0>(); }
        __syncthreads();

        #pragma unroll
        for (int kf = 0; kf < 2; ++kf) {
            const int k0 = kf * 16;
            unsigned A[2][4];
            #pragma unroll
            for (int mt = 0; mt < 2; ++mt) {
                int r = wm * 32 + mt * 16 + g;
                A[mt][0] = *(const unsigned*)&as[cur][r    ][k0     + t * 2];
                A[mt][1] = *(const unsigned*)&as[cur][r + 8][k0     + t * 2];
                A[mt][2] = *(const unsigned*)&as[cur][r    ][k0 + 8 + t * 2];
                A[mt][3] = *(const unsigned*)&as[cur][r + 8][k0 + 8 + t * 2];
            }
            #pragma unroll
            for (int nt = 0; nt < 8; ++nt) {
                int n = wn * 64 + nt * 8 + g;
                unsigned b0 = *(const unsigned*)&bs[cur][n][k0     + t * 2];
                unsigned b1 = *(const unsigned*)&bs[cur][n][k0 + 8 + t * 2];
                mma_bf16(c[0][nt][0], c[0][nt][1], c[0][nt][2], c[0][nt][3],
                         A[0][0], A[0][1], A[0][2], A[0][3], b0, b1);
                mma_bf16(c[1][nt][0], c[1][nt][1], c[1][nt][2], c[1][nt][3],
                         A[1][0], A[1][1], A[1][2], A[1][3], b0, b1);
            }
        }
        __syncthreads();
    }

    #pragma unroll
    for (int mt = 0; mt < 2; ++mt) {
        #pragma unroll
        for (int nt = 0; nt < 8; ++nt) {
            const int col = col0 + wn * 64 + nt * 8 + t * 2;
            const float bi0 = bo[col], bi1 = bo[col + 1];
            const int r0 = row0 + wm * 32 + mt * 16 + g;
            #pragma unroll
            for (int rr = 0; rr < 2; ++rr) {
                const int rowg = r0 + rr * 8;
                const float* res = Qres + (size_t)rowg * Dc + col;
                float2 rv = *(const float2*)res;
                float2 o = make_float2(c[mt][nt][rr * 2 + 0] + bi0 + rv.x,
                                       c[mt][nt][rr * 2 + 1] + bi1 + rv.y);
                *(float2*)(g_y + (size_t)rowg * Dc + col) = o;
            }
        }
    }
}

// ---------------------------------------------------------------------------
// Kernel 4: LayerNorm per row (fp32).
// ---------------------------------------------------------------------------
__global__ __launch_bounds__(256) void ln_kernel(
    const float* __restrict__ gamma, const float* __restrict__ beta,
    float* __restrict__ out)
{
    const int row = blockIdx.x;
    const int tid = threadIdx.x;
    const float* y = g_y + (size_t)row * Dc;

    float4 v = ((const float4*)y)[tid];
    float s  = v.x + v.y + v.z + v.w;
    float q  = v.x * v.x + v.y * v.y + v.z * v.z + v.w * v.w;

    __shared__ float ss[8];
    __shared__ float sq[8];
    #pragma unroll
    for (int o = 16; o > 0; o >>= 1) {
        s += __shfl_xor_sync(0xffffffffu, s, o);
        q += __shfl_xor_sync(0xffffffffu, q, o);
    }
    if ((tid & 31) == 0) { ss[tid >> 5] = s; sq[tid >> 5] = q; }
    __syncthreads();
    s = ss[tid & 7];
    q = sq[tid & 7];
    #pragma unroll
    for (int o = 4; o > 0; o >>= 1) {
        s += __shfl_xor_sync(0xffffffffu, s, o);
        q += __shfl_xor_sync(0xffffffffu, q, o);
    }

    const float mu  = s * (1.0f / Dc);
    const float var = q * (1.0f / Dc) - mu * mu;
    const float inv = rsqrtf(var + 1e-5f);

    float4 gv = ((const float4*)gamma)[tid];
    float4 bv = ((const float4*)beta)[tid];
    float4 o4 = make_float4((v.x - mu) * inv * gv.x + bv.x,
                            (v.y - mu) * inv * gv.y + bv.y,
                            (v.z - mu) * inv * gv.z + bv.z,
                            (v.w - mu) * inv * gv.w + bv.w);
    ((float4*)(out + (size_t)row * Dc))[tid] = o4;
}

// ---------------------------------------------------------------------------
// Launch
// ---------------------------------------------------------------------------
extern "C" void kernel_launch(void* const* d_in, const int* in_sizes, int n_in,
                              void* d_out, int out_size)
{
    const float* Qin  = (const float*)d_in[0];
    const unsigned* mask = (const unsigned*)d_in[3];
    const float* Wq = (const float*)d_in[4];
    const float* bq = (const float*)d_in[5];
    const float* Wk = (const float*)d_in[6];
    const float* bk = (const float*)d_in[7];
    const float* Wv = (const float*)d_in[8];
    const float* bv = (const float*)d_in[9];
    const float* Wo = (const float*)d_in[10];
    const float* bo = (const float*)d_in[11];
    const float* ln_g = (const float*)d_in[12];
    const float* ln_b = (const float*)d_in[13];

    float* out  = (float*)d_out;
    float* attn = out + (size_t)Bc * Sc * Dc;

    pre_kernel       <<<10240, 256>>>(Qin, mask, Wq, Wk, Wv, Wo);
    proj_all_kernel  <<<dim3(Dc / 128, Mc / 128, 3), 256>>>(bq, bk, bv);
    attn_fused_kernel<<<dim3(Sc / 128, BHc), 256>>>(attn);
    oproj_mma_kernel <<<dim3(Dc / 128, Mc / 128), 256>>>(bo, Qin);
    ln_kernel        <<<Mc, 256>>>(ln_g, ln_b, out);
}

// round 17
// speedup vs baseline: 1.0680x; 1.0246x over previous
#include <cuda_runtime.h>
#include <cuda_bf16.h>

#define Bc   2
#define Sc   2048
#define Dc   1024
#define Hc   16
#define DKc  64
#define Mc   (Bc * Sc)        // 4096
#define BHc  (Bc * Hc)        // 32

// exp(0.125*x) == 2^(x * 0.125*log2(e))
#define EXP_SCALE 0.18033688011112042f

// ---------------------------------------------------------------------------
// Scratch (__device__ globals; no cudaMalloc allowed)
// ---------------------------------------------------------------------------
__device__ __align__(16) __nv_bfloat16 g_xb [(size_t)Mc * Dc];          // X bf16 (V path)
__device__ __align__(16) float         g_xtf[(size_t)Mc * Dc];          // X tf32-rounded (QK path)
__device__ __align__(16) __nv_bfloat16 g_wT [4][(size_t)Dc * Dc];       // bf16 W^T ([2],[3] used)
__device__ __align__(16) float         g_wTf[2][(size_t)Dc * Dc];       // tf32-rounded W^T (Wq,Wk)
__device__ __align__(16) float         g_qf [(size_t)BHc * Sc * DKc];   // q tf32-rounded [bh][s][dk]
__device__ __align__(16) float         g_kf [(size_t)BHc * Sc * DKc];   // k tf32-rounded [bh][s][dk]
__device__ __align__(16) __nv_bfloat16 g_kb [(size_t)BHc * Sc * DKc];   // k bf16 (pass-1 sums)
__device__ __align__(16) __nv_bfloat16 g_vT [(size_t)BHc * DKc * Sc];   // v bf16 [bh][dk][s]
__device__ __align__(16) __nv_bfloat16 g_ctxb[(size_t)Mc * Dc];         // ctx bf16
__device__ unsigned g_mask[(size_t)Bc * Sc * (Sc / 32)];                 // bit-packed mask
__device__ __align__(16) float g_y [(size_t)Mc * Dc];                    // pre-LN

// ---------------------------------------------------------------------------
// MMA + async-copy + ldmatrix helpers
// ---------------------------------------------------------------------------
__device__ __forceinline__ void mma_bf16(
    float& c0, float& c1, float& c2, float& c3,
    unsigned a0, unsigned a1, unsigned a2, unsigned a3,
    unsigned b0, unsigned b1)
{
    asm volatile(
        "mma.sync.aligned.m16n8k16.row.col.f32.bf16.bf16.f32 "
        "{%0,%1,%2,%3}, {%4,%5,%6,%7}, {%8,%9}, {%0,%1,%2,%3};\n"
        : "+f"(c0), "+f"(c1), "+f"(c2), "+f"(c3)
        : "r"(a0), "r"(a1), "r"(a2), "r"(a3), "r"(b0), "r"(b1));
}

__device__ __forceinline__ void mma_tf32(
    float& c0, float& c1, float& c2, float& c3,
    unsigned a0, unsigned a1, unsigned a2, unsigned a3,
    unsigned b0, unsigned b1)
{
    asm volatile(
        "mma.sync.aligned.m16n8k8.row.col.f32.tf32.tf32.f32 "
        "{%0,%1,%2,%3}, {%4,%5,%6,%7}, {%8,%9}, {%0,%1,%2,%3};\n"
        : "+f"(c0), "+f"(c1), "+f"(c2), "+f"(c3)
        : "r"(a0), "r"(a1), "r"(a2), "r"(a3), "r"(b0), "r"(b1));
}

__device__ __forceinline__ float f2tf_f(float x)
{
    unsigned r;
    asm("cvt.rna.tf32.f32 %0, %1;" : "=r"(r) : "f"(x));
    return __uint_as_float(r);
}

__device__ __forceinline__ unsigned pack_bf16x2(float a, float b)
{
    unsigned r;
    asm("cvt.rn.bf16x2.f32 %0, %1, %2;" : "=r"(r) : "f"(b), "f"(a));
    return r;
}

__device__ __forceinline__ float ex2(float x)
{
    float r;
    asm("ex2.approx.f32 %0, %1;" : "=f"(r) : "f"(x));
    return r;
}

__device__ __forceinline__ void cp16(void* smem, const void* gmem)
{
    unsigned sa = (unsigned)__cvta_generic_to_shared(smem);
    asm volatile("cp.async.cg.shared.global [%0], [%1], 16;\n"
                 :: "r"(sa), "l"(gmem));
}
__device__ __forceinline__ void cp_commit()
{
    asm volatile("cp.async.commit_group;\n");
}
template<int N> __device__ __forceinline__ void cp_wait()
{
    asm volatile("cp.async.wait_group %0;\n" :: "n"(N));
}

__device__ __forceinline__ void ldm_x4(unsigned& r0, unsigned& r1,
                                       unsigned& r2, unsigned& r3, const void* p)
{
    unsigned a = (unsigned)__cvta_generic_to_shared(p);
    asm volatile("ldmatrix.sync.aligned.m8n8.x4.shared.b16 {%0,%1,%2,%3}, [%4];\n"
                 : "=r"(r0), "=r"(r1), "=r"(r2), "=r"(r3) : "r"(a));
}

__device__ __forceinline__ void stcs2(float* p, float a, float b)
{
    asm volatile("st.global.cs.v2.f32 [%0], {%1, %2};\n"
                 :: "l"(p), "f"(a), "f"(b) : "memory");
}

// ---------------------------------------------------------------------------
// Kernel 0: merged pre-pass.
//   blocks [0,4096):        X -> bf16 + tf32
//   blocks [4096,8192):     W transpose (z = idx>>10)
//   blocks [8192,10240):    mask bit-pack (128 words per block)
// ---------------------------------------------------------------------------
__global__ __launch_bounds__(256) void pre_kernel(
    const float* __restrict__ X, const unsigned* __restrict__ mask,
    const float* __restrict__ W0, const float* __restrict__ W1,
    const float* __restrict__ W2, const float* __restrict__ W3)
{
    __shared__ float tile[32][33];
    const int bid = blockIdx.x;
    const int tid = threadIdx.x;

    if (bid < 4096) {
        size_t i = ((size_t)bid * 256 + tid) * 4;
        float4 v = *(const float4*)(X + i);
        __nv_bfloat162* d = (__nv_bfloat162*)(g_xb + i);
        d[0] = __floats2bfloat162_rn(v.x, v.y);
        d[1] = __floats2bfloat162_rn(v.z, v.w);
        float4 tv = make_float4(f2tf_f(v.x), f2tf_f(v.y), f2tf_f(v.z), f2tf_f(v.w));
        *(float4*)(g_xtf + i) = tv;
    } else if (bid < 8192) {
        const int wb = bid - 4096;
        const int z  = wb >> 10;
        const int li = wb & 1023;
        const float* W = z == 0 ? W0 : z == 1 ? W1 : z == 2 ? W2 : W3;
        const int tx = tid & 31, ty = tid >> 5;
        const int k0 = (li & 31) * 32, n0 = (li >> 5) * 32;
        #pragma unroll
        for (int i = 0; i < 4; ++i)
            tile[ty + i * 8][tx] = W[(size_t)(k0 + ty + i * 8) * Dc + n0 + tx];
        __syncthreads();
        if (z < 2) {
            float* out = g_wTf[z];
            #pragma unroll
            for (int i = 0; i < 4; ++i)
                out[(size_t)(n0 + ty + i * 8) * Dc + k0 + tx] =
                    f2tf_f(tile[tx][ty + i * 8]);
        } else {
            __nv_bfloat16* out = g_wT[z];
            #pragma unroll
            for (int i = 0; i < 4; ++i)
                out[(size_t)(n0 + ty + i * 8) * Dc + k0 + tx] =
                    __float2bfloat16(tile[tx][ty + i * 8]);
        }
    } else {
        const int mb   = bid - 8192;           // 0..2047, 128 words each
        const int warp = tid >> 5, lane = tid & 31;
        const int wbase = mb * 128 + warp * 16;
        #pragma unroll
        for (int k = 0; k < 16; ++k) {
            const int w = wbase + k;
            unsigned v = mask[(size_t)w * 32 + lane];
            unsigned bits = __ballot_sync(0xffffffffu, v != 0);
            if (lane == 0) g_mask[w] = bits;
        }
    }
}

// ---------------------------------------------------------------------------
// Kernel 1: ALL projections in one launch (z in blockIdx.z).
//   z=0: q (tf32, BK=16), z=1: k (tf32, + bf16 copy), z=2: v (bf16, BK=32,
//   ldmatrix fragment loads).
// ---------------------------------------------------------------------------
__global__ __launch_bounds__(256, 2) void proj_all_kernel(
    const float* __restrict__ bq, const float* __restrict__ bk,
    const float* __restrict__ bv)
{
    __shared__ __align__(16) unsigned char smA[20480];
    __shared__ __align__(16) unsigned char smB[20480];

    const int z    = blockIdx.z;
    const int tid  = threadIdx.x;
    const int warp = tid >> 5, lane = tid & 31;
    const int g = lane >> 2, t = lane & 3;
    const int lm = lane >> 3, lr = lane & 7;
    const int wm = warp >> 1, wn = warp & 1;
    const int row0 = blockIdx.y * 128;
    const int col0 = blockIdx.x * 128;

    float c[2][8][4];
    #pragma unroll
    for (int mt = 0; mt < 2; ++mt)
        #pragma unroll
        for (int nt = 0; nt < 8; ++nt)
            #pragma unroll
            for (int q = 0; q < 4; ++q) c[mt][nt][q] = 0.f;

    if (z < 2) {
        const float* Wt   = g_wTf[z];
        const float* bias = z == 0 ? bq : bk;
        float* outp = z == 0 ? g_qf : g_kf;

        float (*as)[128][20] = (float (*)[128][20])smA;
        float (*bs)[128][20] = (float (*)[128][20])smB;

        auto load_stage = [&](int kk, int st) {
            #pragma unroll
            for (int it = 0; it < 2; ++it) {
                int f = tid + it * 256;
                int r = f >> 2, c4 = (f & 3) * 4;
                cp16(&as[st][r][c4], g_xtf + (size_t)(row0 + r) * Dc + kk + c4);
                cp16(&bs[st][r][c4], Wt    + (size_t)(col0 + r) * Dc + kk + c4);
            }
            cp_commit();
        };

        load_stage(0, 0);
        const int nT = Dc / 16;
        for (int tt = 0; tt < nT; ++tt) {
            const int cur = tt & 1;
            if (tt + 1 < nT) { load_stage((tt + 1) * 16, cur ^ 1); cp_wait<1>(); }
            else             { cp_wait<0>(); }
            __syncthreads();

            #pragma unroll
            for (int kf = 0; kf < 2; ++kf) {
                const int k0 = kf * 8;
                unsigned A[2][4];
                #pragma unroll
                for (int mt = 0; mt < 2; ++mt) {
                    int r = wm * 32 + mt * 16 + g;
                    A[mt][0] = __float_as_uint(as[cur][r    ][k0 + t]);
                    A[mt][1] = __float_as_uint(as[cur][r + 8][k0 + t]);
                    A[mt][2] = __float_as_uint(as[cur][r    ][k0 + t + 4]);
                    A[mt][3] = __float_as_uint(as[cur][r + 8][k0 + t + 4]);
                }
                #pragma unroll
                for (int nt = 0; nt < 8; ++nt) {
                    int n = wn * 64 + nt * 8 + g;
                    unsigned b0 = __float_as_uint(bs[cur][n][k0 + t]);
                    unsigned b1 = __float_as_uint(bs[cur][n][k0 + t + 4]);
                    mma_tf32(c[0][nt][0], c[0][nt][1], c[0][nt][2], c[0][nt][3],
                             A[0][0], A[0][1], A[0][2], A[0][3], b0, b1);
                    mma_tf32(c[1][nt][0], c[1][nt][1], c[1][nt][2], c[1][nt][3],
                             A[1][0], A[1][1], A[1][2], A[1][3], b0, b1);
                }
            }
            __syncthreads();
        }

        #pragma unroll
        for (int mt = 0; mt < 2; ++mt) {
            #pragma unroll
            for (int nt = 0; nt < 8; ++nt) {
                const int col = col0 + wn * 64 + nt * 8 + t * 2;
                const int h = col >> 6, dk = col & 63;
                const float bi0 = bias[col], bi1 = bias[col + 1];
                const int r0 = row0 + wm * 32 + mt * 16 + g;
                #pragma unroll
                for (int rr = 0; rr < 2; ++rr) {
                    const int rowg = r0 + rr * 8;
                    const int b = rowg >> 11, s = rowg & 2047;
                    const float v0 = c[mt][nt][rr * 2 + 0] + bi0;
                    const float v1 = c[mt][nt][rr * 2 + 1] + bi1;
                    const size_t off = ((size_t)(b * Hc + h) * Sc + s) * DKc + dk;
                    *(float2*)(outp + off) = make_float2(f2tf_f(v0), f2tf_f(v1));
                    if (z == 1)
                        *(__nv_bfloat162*)(g_kb + off) = __floats2bfloat162_rn(v0, v1);
                }
            }
        }
    } else {
        const __nv_bfloat16* Wt = g_wT[2];

        __nv_bfloat16 (*as)[128][40] = (__nv_bfloat16 (*)[128][40])smA;
        __nv_bfloat16 (*bs)[128][40] = (__nv_bfloat16 (*)[128][40])smB;

        auto load_stage = [&](int kk, int st) {
            #pragma unroll
            for (int it = 0; it < 2; ++it) {
                int f = tid + it * 256;
                int r = f >> 2, c8 = (f & 3) * 8;
                cp16(&as[st][r][c8], g_xb + (size_t)(row0 + r) * Dc + kk + c8);
                cp16(&bs[st][r][c8], Wt   + (size_t)(col0 + r) * Dc + kk + c8);
            }
            cp_commit();
        };

        load_stage(0, 0);
        const int nT = Dc / 32;
        for (int tt = 0; tt < nT; ++tt) {
            const int cur = tt & 1;
            if (tt + 1 < nT) { load_stage((tt + 1) * 32, cur ^ 1); cp_wait<1>(); }
            else             { cp_wait<0>(); }
            __syncthreads();

            #pragma unroll
            for (int kf = 0; kf < 2; ++kf) {
                const int k0 = kf * 16;
                unsigned A[2][4];
                #pragma unroll
                for (int mt = 0; mt < 2; ++mt) {
                    // A fragment via ldmatrix: m&1 -> row-half, m>>1 -> k-half
                    ldm_x4(A[mt][0], A[mt][1], A[mt][2], A[mt][3],
                           &as[cur][wm * 32 + mt * 16 + (lm & 1) * 8 + lr]
                                   [k0 + (lm >> 1) * 8]);
                }
                #pragma unroll
                for (int q = 0; q < 4; ++q) {
                    const int nt0 = 2 * q;
                    // B fragments via ldmatrix: m>>1 -> n-tile, m&1 -> k-half
                    unsigned r0, r1, r2, r3;
                    ldm_x4(r0, r1, r2, r3,
                           &bs[cur][wn * 64 + (nt0 + (lm >> 1)) * 8 + lr]
                                   [k0 + (lm & 1) * 8]);
                    mma_bf16(c[0][nt0][0], c[0][nt0][1], c[0][nt0][2], c[0][nt0][3],
                             A[0][0], A[0][1], A[0][2], A[0][3], r0, r1);
                    mma_bf16(c[1][nt0][0], c[1][nt0][1], c[1][nt0][2], c[1][nt0][3],
                             A[1][0], A[1][1], A[1][2], A[1][3], r0, r1);
                    mma_bf16(c[0][nt0 + 1][0], c[0][nt0 + 1][1], c[0][nt0 + 1][2], c[0][nt0 + 1][3],
                             A[0][0], A[0][1], A[0][2], A[0][3], r2, r3);
                    mma_bf16(c[1][nt0 + 1][0], c[1][nt0 + 1][1], c[1][nt0 + 1][2], c[1][nt0 + 1][3],
                             A[1][0], A[1][1], A[1][2], A[1][3], r2, r3);
                }
            }
            __syncthreads();
        }

        #pragma unroll
        for (int mt = 0; mt < 2; ++mt) {
            #pragma unroll
            for (int nt = 0; nt < 8; ++nt) {
                const int col = col0 + wn * 64 + nt * 8 + t * 2;
                const int h = col >> 6, dk = col & 63;
                const float bi0 = bv[col], bi1 = bv[col + 1];
                const int r0 = row0 + wm * 32 + mt * 16 + g;
                #pragma unroll
                for (int rr = 0; rr < 2; ++rr) {
                    const int rowg = r0 + rr * 8;
                    const int b = rowg >> 11, s = rowg & 2047;
                    g_vT[((size_t)(b * Hc + h) * DKc + dk    ) * Sc + s] =
                        __float2bfloat16(c[mt][nt][rr * 2 + 0] + bi0);
                    g_vT[((size_t)(b * Hc + h) * DKc + dk + 1) * Sc + s] =
                        __float2bfloat16(c[mt][nt][rr * 2 + 1] + bi1);
                }
            }
        }
    }
}

// ---------------------------------------------------------------------------
// Kernel 2: FUSED attention, static smem, 2 blocks/SM (R14 configuration).
// ---------------------------------------------------------------------------
__global__ __launch_bounds__(256, 2) void attn_fused_kernel(float* __restrict__ attn)
{
    const int bh = blockIdx.y;
    const int i0 = blockIdx.x * 128;
    const int b  = bh >> 4, h = bh & 15;

    __shared__ __align__(16) unsigned char sbuf[44032];
    float (*qs)[68] = (float (*)[68])sbuf;
    __nv_bfloat16 (*kb0)[72] = (__nv_bfloat16 (*)[72])sbuf;
    __nv_bfloat16 (*kb1)[72] = (__nv_bfloat16 (*)[72])(sbuf + 18432);
    float (*ks0)[68] = (float (*)[68])sbuf;
    float (*ks1)[68] = (float (*)[68])(sbuf + 17408);
    __nv_bfloat16 (*vs)[72] = (__nv_bfloat16 (*)[72])(sbuf + 34816);

    const int tid = threadIdx.x, warp = tid >> 5, lane = tid & 31;
    const int g = lane >> 2, t = lane & 3;
    const int lm = lane >> 3, lr = lane & 7;

    const float* qbase = g_qf + ((size_t)bh * Sc + i0) * DKc;
    const float* kbase = g_kf + (size_t)bh * Sc * DKc;
    const __nv_bfloat16* kbbase = g_kb + (size_t)bh * Sc * DKc;
    const __nv_bfloat16* vbase  = g_vT + (size_t)bh * DKc * Sc;

    #pragma unroll
    for (int it = 0; it < 8; ++it) {
        int f = tid + it * 256;
        int r = f >> 4, c4 = (f & 15) * 4;
        *(float4*)&qs[r][c4] = *(const float4*)(qbase + (size_t)r * DKc + c4);
    }
    __syncthreads();

    unsigned A[8][4];    // tf32 fragments (pass 2)
    unsigned Ab[4][4];   // bf16 fragments (pass 1)
    {
        const int r = warp * 16 + g;
        #pragma unroll
        for (int kf = 0; kf < 8; ++kf) {
            const int k0 = kf * 8;
            A[kf][0] = __float_as_uint(qs[r    ][k0 + t]);
            A[kf][1] = __float_as_uint(qs[r + 8][k0 + t]);
            A[kf][2] = __float_as_uint(qs[r    ][k0 + t + 4]);
            A[kf][3] = __float_as_uint(qs[r + 8][k0 + t + 4]);
        }
        #pragma unroll
        for (int kf = 0; kf < 4; ++kf) {
            const int k0 = kf * 16;
            Ab[kf][0] = pack_bf16x2(qs[r    ][k0     + t * 2], qs[r    ][k0     + t * 2 + 1]);
            Ab[kf][1] = pack_bf16x2(qs[r + 8][k0     + t * 2], qs[r + 8][k0     + t * 2 + 1]);
            Ab[kf][2] = pack_bf16x2(qs[r    ][k0 + 8 + t * 2], qs[r    ][k0 + 8 + t * 2 + 1]);
            Ab[kf][3] = pack_bf16x2(qs[r + 8][k0 + 8 + t * 2], qs[r + 8][k0 + 8 + t * 2 + 1]);
        }
    }
    __syncthreads();

    const int ig0 = i0 + warp * 16 + g;
    const int ig1 = ig0 + 8;
    const unsigned* mp0 = g_mask + ((size_t)b * Sc + ig0) * (Sc / 32);
    const unsigned* mp1 = g_mask + ((size_t)b * Sc + ig1) * (Sc / 32);
    float* arow0 = attn + ((size_t)bh * Sc + ig0) * Sc;
    float* arow1 = attn + ((size_t)bh * Sc + ig1) * Sc;

    auto load_kb128 = [&](int jj, int st) {   // 128 rows of bf16 K
        __nv_bfloat16 (*dst)[72] = st ? kb1 : kb0;
        #pragma unroll
        for (int it = 0; it < 4; ++it) {
            int f = tid + it * 256;
            int r = f >> 3, c8 = (f & 7) * 8;
            cp16(&dst[r][c8], kbbase + (size_t)(jj + r) * DKc + c8);
        }
        cp_commit();
    };
    auto load_k = [&](int jj, int st) {
        float (*dst)[68] = st ? ks1 : ks0;
        #pragma unroll
        for (int it = 0; it < 4; ++it) {
            int f = tid + it * 256;
            int r = f >> 4, c4 = (f & 15) * 4;
            cp16(&dst[r][c4], kbase + (size_t)(jj + r) * DKc + c4);
        }
        cp_commit();
    };
    auto load_v = [&](int jj) {
        #pragma unroll
        for (int it = 0; it < 2; ++it) {
            int f = tid + it * 256;
            int dk = f >> 3, c8 = (f & 7) * 8;
            cp16(&vs[dk][c8], vbase + (size_t)dk * Sc + jj + c8);
        }
        cp_commit();
    };

    // ---------------- pass 1: row sums (bf16 MMA, 128-row tiles) ------------
    float rsum0 = 0.f, rsum1 = 0.f;
    load_kb128(0, 0);
    for (int jj = 0; jj < Sc; jj += 128) {
        const int cur = (jj >> 7) & 1;
        if (jj + 128 < Sc) { load_kb128(jj + 128, cur ^ 1); cp_wait<1>(); }
        else               { cp_wait<0>(); }
        __syncthreads();
        __nv_bfloat16 (*kb)[72] = cur ? kb1 : kb0;

        #pragma unroll
        for (int sub = 0; sub < 2; ++sub) {
            const int jje = jj + sub * 64;
            __nv_bfloat16 (*kbs)[72] = (__nv_bfloat16 (*)[72])(kb + sub * 64);

            float c[8][4];
            #pragma unroll
            for (int nt = 0; nt < 8; ++nt)
                #pragma unroll
                for (int q = 0; q < 4; ++q) c[nt][q] = 0.f;
            #pragma unroll
            for (int kf = 0; kf < 4; ++kf) {
                const int k0 = kf * 16;
                #pragma unroll
                for (int q = 0; q < 4; ++q) {
                    const int nt0 = 2 * q;
                    unsigned r0, r1, r2, r3;
                    ldm_x4(r0, r1, r2, r3,
                           &kbs[(nt0 + (lm >> 1)) * 8 + lr][k0 + (lm & 1) * 8]);
                    mma_bf16(c[nt0][0], c[nt0][1], c[nt0][2], c[nt0][3],
                             Ab[kf][0], Ab[kf][1], Ab[kf][2], Ab[kf][3], r0, r1);
                    mma_bf16(c[nt0 + 1][0], c[nt0 + 1][1], c[nt0 + 1][2], c[nt0 + 1][3],
                             Ab[kf][0], Ab[kf][1], Ab[kf][2], Ab[kf][3], r2, r3);
                }
            }

            const unsigned m00 = mp0[jje >> 5], m01 = mp0[(jje >> 5) + 1];
            const unsigned m10 = mp1[jje >> 5], m11 = mp1[(jje >> 5) + 1];
            #pragma unroll
            for (int nt = 0; nt < 8; ++nt) {
                const int jl = nt * 8 + t * 2;
                const unsigned w0 = (jl & 32) ? m01 : m00;
                const unsigned w1 = (jl & 32) ? m11 : m10;
                const int sh = jl & 31;
                rsum0 += (((w0 >> sh)       & 1u) ? 0.f : ex2(c[nt][0] * EXP_SCALE))
                       + (((w0 >> (sh + 1)) & 1u) ? 0.f : ex2(c[nt][1] * EXP_SCALE));
                rsum1 += (((w1 >> sh)       & 1u) ? 0.f : ex2(c[nt][2] * EXP_SCALE))
                       + (((w1 >> (sh + 1)) & 1u) ? 0.f : ex2(c[nt][3] * EXP_SCALE));
            }
        }
        __syncthreads();
    }
    rsum0 += __shfl_xor_sync(0xffffffffu, rsum0, 1);
    rsum0 += __shfl_xor_sync(0xffffffffu, rsum0, 2);
    rsum1 += __shfl_xor_sync(0xffffffffu, rsum1, 1);
    rsum1 += __shfl_xor_sync(0xffffffffu, rsum1, 2);
    const float invl0 = 1.0f / rsum0;
    const float invl1 = 1.0f / rsum1;

    // ---------------- pass 2: write p, ctx = p @ V (tf32 scores) ----------
    float ctx[8][4];
    #pragma unroll
    for (int nt = 0; nt < 8; ++nt)
        #pragma unroll
        for (int q = 0; q < 4; ++q) ctx[nt][q] = 0.f;

    load_k(0, 0);
    for (int jj = 0; jj < Sc; jj += 64) {
        const int cur = (jj >> 6) & 1;
        load_v(jj);
        if (jj + 64 < Sc) { load_k(jj + 64, cur ^ 1); cp_wait<1>(); }
        else              { cp_wait<0>(); }
        __syncthreads();
        float (*ks)[68] = cur ? ks1 : ks0;

        #pragma unroll
        for (int half = 0; half < 2; ++half) {
            float c[4][4];
            #pragma unroll
            for (int ntl = 0; ntl < 4; ++ntl)
                #pragma unroll
                for (int q = 0; q < 4; ++q) c[ntl][q] = 0.f;

            #pragma unroll
            for (int kf = 0; kf < 8; ++kf) {
                const int k0 = kf * 8;
                #pragma unroll
                for (int ntl = 0; ntl < 4; ++ntl) {
                    const int n = (half * 4 + ntl) * 8 + g;
                    unsigned b0 = __float_as_uint(ks[n][k0 + t]);
                    unsigned b1 = __float_as_uint(ks[n][k0 + t + 4]);
                    mma_tf32(c[ntl][0], c[ntl][1], c[ntl][2], c[ntl][3],
                             A[kf][0], A[kf][1], A[kf][2], A[kf][3], b0, b1);
                }
            }

            const unsigned w0 = mp0[(jj >> 5) + half];
            const unsigned w1 = mp1[(jj >> 5) + half];

            unsigned pf[4][2];
            #pragma unroll
            for (int ntl = 0; ntl < 4; ++ntl) {
                const int nt = half * 4 + ntl;
                const int jl = nt * 8 + t * 2;
                const int sh = jl & 31;
                float p0 = ((w0 >> sh)       & 1u) ? 0.f : ex2(c[ntl][0] * EXP_SCALE) * invl0;
                float p1 = ((w0 >> (sh + 1)) & 1u) ? 0.f : ex2(c[ntl][1] * EXP_SCALE) * invl0;
                float p2 = ((w1 >> sh)       & 1u) ? 0.f : ex2(c[ntl][2] * EXP_SCALE) * invl1;
                float p3 = ((w1 >> (sh + 1)) & 1u) ? 0.f : ex2(c[ntl][3] * EXP_SCALE) * invl1;
                stcs2(arow0 + jj + jl, p0, p1);
                stcs2(arow1 + jj + jl, p2, p3);
                pf[ntl][0] = pack_bf16x2(p0, p1);
                pf[ntl][1] = pack_bf16x2(p2, p3);
            }

            #pragma unroll
            for (int kfl = 0; kfl < 2; ++kfl) {
                const int k0 = (half * 2 + kfl) * 16;
                const unsigned a0 = pf[2 * kfl    ][0];
                const unsigned a1 = pf[2 * kfl    ][1];
                const unsigned a2 = pf[2 * kfl + 1][0];
                const unsigned a3 = pf[2 * kfl + 1][1];
                #pragma unroll
                for (int q = 0; q < 4; ++q) {
                    const int nt0 = 2 * q;
                    unsigned r0, r1, r2, r3;
                    ldm_x4(r0, r1, r2, r3,
                           &vs[(nt0 + (lm >> 1)) * 8 + lr][k0 + (lm & 1) * 8]);
                    mma_bf16(ctx[nt0][0], ctx[nt0][1], ctx[nt0][2], ctx[nt0][3],
                             a0, a1, a2, a3, r0, r1);
                    mma_bf16(ctx[nt0 + 1][0], ctx[nt0 + 1][1], ctx[nt0 + 1][2], ctx[nt0 + 1][3],
                             a0, a1, a2, a3, r2, r3);
                }
            }
        }
        __syncthreads();
    }

    const int s = i0 + warp * 16 + g;
    const size_t crow0 = ((size_t)b * Sc + s)     * Dc;
    const size_t crow1 = ((size_t)b * Sc + s + 8) * Dc;
    #pragma unroll
    for (int nt = 0; nt < 8; ++nt) {
        const int col = h * DKc + nt * 8 + t * 2;
        *(__nv_bfloat162*)&g_ctxb[crow0 + col] = __floats2bfloat162_rn(ctx[nt][0], ctx[nt][1]);
        *(__nv_bfloat162*)&g_ctxb[crow1 + col] = __floats2bfloat162_rn(ctx[nt][2], ctx[nt][3]);
    }
}

// ---------------------------------------------------------------------------
// Kernel 3: output projection, bf16 MMA, cp.async 2-stage, ldmatrix frags.
// ---------------------------------------------------------------------------
__global__ __launch_bounds__(256, 2) void oproj_mma_kernel(
    const float* __restrict__ bo, const float* __restrict__ Qres)
{
    const __nv_bfloat16* Wt = g_wT[3];

    __shared__ __align__(16) __nv_bfloat16 as[2][128][40];
    __shared__ __align__(16) __nv_bfloat16 bs[2][128][40];

    const int tid  = threadIdx.x;
    const int warp = tid >> 5, lane = tid & 31;
    const int g = lane >> 2, t = lane & 3;
    const int lm = lane >> 3, lr = lane & 7;
    const int wm = warp >> 1, wn = warp & 1;
    const int row0 = blockIdx.y * 128;
    const int col0 = blockIdx.x * 128;

    float c[2][8][4];
    #pragma unroll
    for (int mt = 0; mt < 2; ++mt)
        #pragma unroll
        for (int nt = 0; nt < 8; ++nt)
            #pragma unroll
            for (int q = 0; q < 4; ++q) c[mt][nt][q] = 0.f;

    auto load_stage = [&](int kk, int st) {
        #pragma unroll
        for (int it = 0; it < 2; ++it) {
            int f = tid + it * 256;
            int r = f >> 2, c8 = (f & 3) * 8;
            cp16(&as[st][r][c8], g_ctxb + (size_t)(row0 + r) * Dc + kk + c8);
            cp16(&bs[st][r][c8], Wt     + (size_t)(col0 + r) * Dc + kk + c8);
        }
        cp_commit();
    };

    load_stage(0, 0);

    const int nT = Dc / 32;
    for (int tt = 0; tt < nT; ++tt) {
        const int cur = tt & 1;
        if (tt + 1 < nT) { load_stage((tt + 1) * 32, cur ^ 1); cp_wait<1>(); }
        else             { cp_wait<0>(); }
        __syncthreads();

        #pragma unroll
        for (int kf = 0; kf < 2; ++kf) {
            const int k0 = kf * 16;
            unsigned A[2][4];
            #pragma unroll
            for (int mt = 0; mt < 2; ++mt) {
                // A fragment via ldmatrix: m&1 -> row-half, m>>1 -> k-half
                ldm_x4(A[mt][0], A[mt][1], A[mt][2], A[mt][3],
                       &as[cur][wm * 32 + mt * 16 + (lm & 1) * 8 + lr]
                               [k0 + (lm >> 1) * 8]);
            }
            #pragma unroll
            for (int q = 0; q < 4; ++q) {
                const int nt0 = 2 * q;
                // B fragments via ldmatrix: m>>1 -> n-tile, m&1 -> k-half
                unsigned r0, r1, r2, r3;
                ldm_x4(r0, r1, r2, r3,
                       &bs[cur][wn * 64 + (nt0 + (lm >> 1)) * 8 + lr]
                               [k0 + (lm & 1) * 8]);
                mma_bf16(c[0][nt0][0], c[0][nt0][1], c[0][nt0][2], c[0][nt0][3],
                         A[0][0], A[0][1], A[0][2], A[0][3], r0, r1);
                mma_bf16(c[1][nt0][0], c[1][nt0][1], c[1][nt0][2], c[1][nt0][3],
                         A[1][0], A[1][1], A[1][2], A[1][3], r0, r1);
                mma_bf16(c[0][nt0 + 1][0], c[0][nt0 + 1][1], c[0][nt0 + 1][2], c[0][nt0 + 1][3],
                         A[0][0], A[0][1], A[0][2], A[0][3], r2, r3);
                mma_bf16(c[1][nt0 + 1][0], c[1][nt0 + 1][1], c[1][nt0 + 1][2], c[1][nt0 + 1][3],
                         A[1][0], A[1][1], A[1][2], A[1][3], r2, r3);
            }
        }
        __syncthreads();
    }

    #pragma unroll
    for (int mt = 0; mt < 2; ++mt) {
        #pragma unroll
        for (int nt = 0; nt < 8; ++nt) {
            const int col = col0 + wn * 64 + nt * 8 + t * 2;
            const float bi0 = bo[col], bi1 = bo[col + 1];
            const int r0 = row0 + wm * 32 + mt * 16 + g;
            #pragma unroll
            for (int rr = 0; rr < 2; ++rr) {
                const int rowg = r0 + rr * 8;
                const float* res = Qres + (size_t)rowg * Dc + col;
                float2 rv = *(const float2*)res;
                float2 o = make_float2(c[mt][nt][rr * 2 + 0] + bi0 + rv.x,
                                       c[mt][nt][rr * 2 + 1] + bi1 + rv.y);
                *(float2*)(g_y + (size_t)rowg * Dc + col) = o;
            }
        }
    }
}

// ---------------------------------------------------------------------------
// Kernel 4: LayerNorm per row (fp32).
// ---------------------------------------------------------------------------
__global__ __launch_bounds__(256) void ln_kernel(
    const float* __restrict__ gamma, const float* __restrict__ beta,
    float* __restrict__ out)
{
    const int row = blockIdx.x;
    const int tid = threadIdx.x;
    const float* y = g_y + (size_t)row * Dc;

    float4 v = ((const float4*)y)[tid];
    float s  = v.x + v.y + v.z + v.w;
    float q  = v.x * v.x + v.y * v.y + v.z * v.z + v.w * v.w;

    __shared__ float ss[8];
    __shared__ float sq[8];
    #pragma unroll
    for (int o = 16; o > 0; o >>= 1) {
        s += __shfl_xor_sync(0xffffffffu, s, o);
        q += __shfl_xor_sync(0xffffffffu, q, o);
    }
    if ((tid & 31) == 0) { ss[tid >> 5] = s; sq[tid >> 5] = q; }
    __syncthreads();
    s = ss[tid & 7];
    q = sq[tid & 7];
    #pragma unroll
    for (int o = 4; o > 0; o >>= 1) {
        s += __shfl_xor_sync(0xffffffffu, s, o);
        q += __shfl_xor_sync(0xffffffffu, q, o);
    }

    const float mu  = s * (1.0f / Dc);
    const float var = q * (1.0f / Dc) - mu * mu;
    const float inv = rsqrtf(var + 1e-5f);

    float4 gv = ((const float4*)gamma)[tid];
    float4 bv = ((const float4*)beta)[tid];
    float4 o4 = make_float4((v.x - mu) * inv * gv.x + bv.x,
                            (v.y - mu) * inv * gv.y + bv.y,
                            (v.z - mu) * inv * gv.z + bv.z,
                            (v.w - mu) * inv * gv.w + bv.w);
    ((float4*)(out + (size_t)row * Dc))[tid] = o4;
}

// ---------------------------------------------------------------------------
// Launch
// ---------------------------------------------------------------------------
extern "C" void kernel_launch(void* const* d_in, const int* in_sizes, int n_in,
                              void* d_out, int out_size)
{
    const float* Qin  = (const float*)d_in[0];
    const unsigned* mask = (const unsigned*)d_in[3];
    const float* Wq = (const float*)d_in[4];
    const float* bq = (const float*)d_in[5];
    const float* Wk = (const float*)d_in[6];
    const float* bk = (const float*)d_in[7];
    const float* Wv = (const float*)d_in[8];
    const float* bv = (const float*)d_in[9];
    const float* Wo = (const float*)d_in[10];
    const float* bo = (const float*)d_in[11];
    const float* ln_g = (const float*)d_in[12];
    const float* ln_b = (const float*)d_in[13];

    float* out  = (float*)d_out;
    float* attn = out + (size_t)Bc * Sc * Dc;

    pre_kernel       <<<10240, 256>>>(Qin, mask, Wq, Wk, Wv, Wo);
    proj_all_kernel  <<<dim3(Dc / 128, Mc / 128, 3), 256>>>(bq, bk, bv);
    attn_fused_kernel<<<dim3(Sc / 128, BHc), 256>>>(attn);
    oproj_mma_kernel <<<dim3(Dc / 128, Mc / 128), 256>>>(bo, Qin);
    ln_kernel        <<<Mc, 256>>>(ln_g, ln_b, out);
}